// round 5
// baseline (speedup 1.0000x reference)
#include <cuda_runtime.h>
#include <cuda_bf16.h>
#include <mma.h>

using namespace nvcuda;

// ---------------- problem constants ----------------
#define NBATCH   64
#define SEQ      256
#define BT       16384      // NBATCH*SEQ
#define C        64
#define NH       8
#define HS       8
#define DFF      256
#define NLAYER   10
#define VOCAB    8000

// ---------------- scratch (static device, no allocs) ----------------
__device__ float g_x  [BT * C];
__device__ float g_h  [BT * C];
__device__ float g_q  [BT * C];
__device__ float g_k  [BT * C];
__device__ float g_v  [BT * C];
__device__ float g_att[BT * C];
__device__ float g_ff [BT * DFF];

// ---------------- embedding: x = tok_emb[idx] + pos_emb ----------------
__global__ void embed_kernel(const int* __restrict__ idx,
                             const float* __restrict__ tok,
                             const float* __restrict__ pos,
                             float* __restrict__ x)
{
    int i = blockIdx.x * blockDim.x + threadIdx.x;   // one float4 per thread
    int r = i >> 4;
    int c = (i & 15) << 2;
    if (r >= BT) return;
    int tk = idx[r];
    float4 a = *(const float4*)(tok + (size_t)tk * C + c);
    float4 p = *(const float4*)(pos + (size_t)(r & (SEQ - 1)) * C + c);
    *(float4*)(x + (size_t)r * C + c) =
        make_float4(a.x + p.x, a.y + p.y, a.z + p.z, a.w + p.w);
}

// ---------------- layernorm: one warp per row of 64 ----------------
__global__ void ln_kernel(const float* __restrict__ in, float* __restrict__ out,
                          const float* __restrict__ g, const float* __restrict__ b)
{
    int gw   = (blockIdx.x * blockDim.x + threadIdx.x) >> 5;
    int lane = threadIdx.x & 31;
    if (gw >= BT) return;
    float2 v = *(const float2*)(in + (size_t)gw * C + lane * 2);
    float s = v.x + v.y;
#pragma unroll
    for (int o = 16; o; o >>= 1) s += __shfl_xor_sync(0xffffffffu, s, o);
    float mu = s * (1.0f / 64.0f);
    float dx = v.x - mu, dy = v.y - mu;
    float sq = dx * dx + dy * dy;
#pragma unroll
    for (int o = 16; o; o >>= 1) sq += __shfl_xor_sync(0xffffffffu, sq, o);
    float inv = rsqrtf(sq * (1.0f / 64.0f) + 1e-5f);
    float2 gg = *(const float2*)(g + lane * 2);
    float2 bb = *(const float2*)(b + lane * 2);
    float2 o2 = make_float2(dx * inv * gg.x + bb.x, dy * inv * gg.y + bb.y);
    *(float2*)(out + (size_t)gw * C + lane * 2) = o2;
}

// ---------------- fp32 GEMM: out[M,N] = A[M,K] @ W[K,N] (+bias)(+res)(relu) ----------
// Tile 64x64, 64 threads, 8x8 register micro-tiles. K in {64,256}, N in {64,256}.
// flags: 1=bias, 2=residual(add res, ld=N), 4=relu
template<int K>
__global__ __launch_bounds__(64)
void gemm_kernel(const float* __restrict__ A, const float* __restrict__ W,
                 const float* __restrict__ bias, const float* __restrict__ res,
                 float* __restrict__ out, int N, int flags)
{
    __shared__ __align__(16) float As[64][64];   // transposed: As[k][m]
    __shared__ __align__(16) float Ws[64][68];   // Ws[k][n], padded

    int m0 = blockIdx.x * 64;
    int n0 = blockIdx.y * 64;
    int t  = threadIdx.x;
    int tx = t & 7, ty = t >> 3;

    float acc[8][8];
#pragma unroll
    for (int i = 0; i < 8; i++)
#pragma unroll
        for (int j = 0; j < 8; j++) acc[i][j] = 0.0f;

    for (int kc = 0; kc < K; kc += 64) {
        const float4* arow = (const float4*)(A + (size_t)(m0 + t) * K + kc);
#pragma unroll
        for (int i = 0; i < 16; i++) {
            float4 a4 = arow[i];
            As[4 * i + 0][t] = a4.x;
            As[4 * i + 1][t] = a4.y;
            As[4 * i + 2][t] = a4.z;
            As[4 * i + 3][t] = a4.w;
        }
        const float4* wrow = (const float4*)(W + (size_t)(kc + t) * N + n0);
#pragma unroll
        for (int i = 0; i < 16; i++) {
            *(float4*)&Ws[t][4 * i] = wrow[i];
        }
        __syncthreads();

#pragma unroll 4
        for (int kk = 0; kk < 64; kk++) {
            float4 a0 = *(const float4*)&As[kk][ty * 8];
            float4 a1 = *(const float4*)&As[kk][ty * 8 + 4];
            float4 b0 = *(const float4*)&Ws[kk][tx * 8];
            float4 b1 = *(const float4*)&Ws[kk][tx * 8 + 4];
            float av[8] = {a0.x, a0.y, a0.z, a0.w, a1.x, a1.y, a1.z, a1.w};
            float bv[8] = {b0.x, b0.y, b0.z, b0.w, b1.x, b1.y, b1.z, b1.w};
#pragma unroll
            for (int i = 0; i < 8; i++)
#pragma unroll
                for (int j = 0; j < 8; j++)
                    acc[i][j] = fmaf(av[i], bv[j], acc[i][j]);
        }
        __syncthreads();
    }

    // epilogue
    float bv2[8];
#pragma unroll
    for (int j = 0; j < 8; j++)
        bv2[j] = (flags & 1) ? bias[n0 + tx * 8 + j] : 0.0f;

#pragma unroll
    for (int i = 0; i < 8; i++) {
        int row = m0 + ty * 8 + i;
        size_t ro = (size_t)row * N + n0 + tx * 8;
        float r0[8];
#pragma unroll
        for (int j = 0; j < 8; j++) r0[j] = acc[i][j] + bv2[j];
        if (flags & 2) {
            float4 e0 = *(const float4*)(res + ro);
            float4 e1 = *(const float4*)(res + ro + 4);
            r0[0] += e0.x; r0[1] += e0.y; r0[2] += e0.z; r0[3] += e0.w;
            r0[4] += e1.x; r0[5] += e1.y; r0[6] += e1.z; r0[7] += e1.w;
        }
        if (flags & 4) {
#pragma unroll
            for (int j = 0; j < 8; j++) r0[j] = fmaxf(r0[j], 0.0f);
        }
        *(float4*)(out + ro)     = make_float4(r0[0], r0[1], r0[2], r0[3]);
        *(float4*)(out + ro + 4) = make_float4(r0[4], r0[5], r0[6], r0[7]);
    }
}

// ---------------- attention: one block per (b,h), flash online softmax --------
__global__ __launch_bounds__(256)
void attn_kernel(const float* __restrict__ q, const float* __restrict__ k,
                 const float* __restrict__ v, float* __restrict__ o)
{
    __shared__ float4 ks[SEQ][2];
    __shared__ float4 vs[SEQ][2];
    int b = blockIdx.x >> 3;
    int h = blockIdx.x & 7;
    int t = threadIdx.x;
    size_t base = (size_t)(b * SEQ + t) * C + h * HS;

    ks[t][0] = *(const float4*)(k + base);
    ks[t][1] = *(const float4*)(k + base + 4);
    vs[t][0] = *(const float4*)(v + base);
    vs[t][1] = *(const float4*)(v + base + 4);
    float4 q0 = *(const float4*)(q + base);
    float4 q1 = *(const float4*)(q + base + 4);
    __syncthreads();

    float m = -1e30f, s = 0.0f;
    float o0 = 0, o1 = 0, o2 = 0, o3 = 0, o4 = 0, o5 = 0, o6 = 0, o7 = 0;
    for (int j = 0; j <= t; j++) {
        float4 k0 = ks[j][0], k1 = ks[j][1];
        float sc = q0.x * k0.x + q0.y * k0.y + q0.z * k0.z + q0.w * k0.w
                 + q1.x * k1.x + q1.y * k1.y + q1.z * k1.z + q1.w * k1.w;
        sc *= 0.125f;                       // scale = n_embd^-0.5 = 1/8
        float mn = fmaxf(m, sc);
        float f  = __expf(m - mn);
        float p  = __expf(sc - mn);
        s = s * f + p;
        float4 v0 = vs[j][0], v1 = vs[j][1];
        o0 = o0 * f + p * v0.x;  o1 = o1 * f + p * v0.y;
        o2 = o2 * f + p * v0.z;  o3 = o3 * f + p * v0.w;
        o4 = o4 * f + p * v1.x;  o5 = o5 * f + p * v1.y;
        o6 = o6 * f + p * v1.z;  o7 = o7 * f + p * v1.w;
        m = mn;
    }
    float inv = 1.0f / s;
    *(float4*)(o + base)     = make_float4(o0 * inv, o1 * inv, o2 * inv, o3 * inv);
    *(float4*)(o + base + 4) = make_float4(o4 * inv, o5 * inv, o6 * inv, o7 * inv);
}

// ---------------- LM head: tf32 WMMA, 64x64 tiles, fused bias ----------------
__global__ __launch_bounds__(256)
void head_kernel(const float* __restrict__ X, const float* __restrict__ Wh,
                 const float* __restrict__ bh, float* __restrict__ out)
{
    __shared__ __align__(16) float As[64][64];
    __shared__ __align__(16) float Bs[64][64];
    int m0 = blockIdx.x * 64;
    int n0 = blockIdx.y * 64;
    int tid = threadIdx.x;

#pragma unroll
    for (int i = 0; i < 4; i++) {
        int u = tid + 256 * i;
        int r = u >> 4, c = (u & 15) << 2;
        *(float4*)&As[r][c] = *(const float4*)(X + (size_t)(m0 + r) * C + c);
        *(float4*)&Bs[r][c] = *(const float4*)(Wh + (size_t)r * VOCAB + n0 + c);
    }
    __syncthreads();

    int wid = tid >> 5;
    int wm = wid >> 1;      // 0..3 -> M offset 16*wm
    int wn = wid & 1;       // 0..1 -> N offset 32*wn (two 16-wide subtiles)

    wmma::fragment<wmma::matrix_a, 16, 16, 8, wmma::precision::tf32, wmma::row_major> fa;
    wmma::fragment<wmma::matrix_b, 16, 16, 8, wmma::precision::tf32, wmma::row_major> fb;
    wmma::fragment<wmma::accumulator, 16, 16, 8, float> fc0, fc1;
    wmma::fill_fragment(fc0, 0.0f);
    wmma::fill_fragment(fc1, 0.0f);

#pragma unroll
    for (int kk = 0; kk < 8; kk++) {
        wmma::load_matrix_sync(fa, &As[wm * 16][kk * 8], 64);
#pragma unroll
        for (int e = 0; e < fa.num_elements; e++) fa.x[e] = wmma::__float_to_tf32(fa.x[e]);

        wmma::load_matrix_sync(fb, &Bs[kk * 8][wn * 32], 64);
#pragma unroll
        for (int e = 0; e < fb.num_elements; e++) fb.x[e] = wmma::__float_to_tf32(fb.x[e]);
        wmma::mma_sync(fc0, fa, fb, fc0);

        wmma::load_matrix_sync(fb, &Bs[kk * 8][wn * 32 + 16], 64);
#pragma unroll
        for (int e = 0; e < fb.num_elements; e++) fb.x[e] = wmma::__float_to_tf32(fb.x[e]);
        wmma::mma_sync(fc1, fa, fb, fc1);
    }
    __syncthreads();     // everyone done reading As before reuse as C tile

    wmma::store_matrix_sync(&As[wm * 16][wn * 32],      fc0, 64, wmma::mem_row_major);
    wmma::store_matrix_sync(&As[wm * 16][wn * 32 + 16], fc1, 64, wmma::mem_row_major);
    __syncthreads();

#pragma unroll
    for (int i = 0; i < 4; i++) {
        int u = tid + 256 * i;
        int r = u >> 4, c = (u & 15) << 2;
        float4 cv = *(float4*)&As[r][c];
        float4 bb = *(const float4*)(bh + n0 + c);
        *(float4*)(out + (size_t)(m0 + r) * VOCAB + n0 + c) =
            make_float4(cv.x + bb.x, cv.y + bb.y, cv.z + bb.z, cv.w + bb.w);
    }
}

// ---------------- launch ----------------
extern "C" void kernel_launch(void* const* d_in, const int* in_sizes, int n_in,
                              void* d_out, int out_size)
{
    const int*   idx    = (const int*)  d_in[0];
    const float* tok    = (const float*)d_in[1];
    const float* pos    = (const float*)d_in[2];
    const float* wq     = (const float*)d_in[3];
    const float* wk     = (const float*)d_in[4];
    const float* wv     = (const float*)d_in[5];
    const float* w_proj = (const float*)d_in[6];
    const float* b_proj = (const float*)d_in[7];
    const float* ln1_g  = (const float*)d_in[8];
    const float* ln1_b  = (const float*)d_in[9];
    const float* ln2_g  = (const float*)d_in[10];
    const float* ln2_b  = (const float*)d_in[11];
    const float* w1     = (const float*)d_in[12];
    const float* b1     = (const float*)d_in[13];
    const float* w2     = (const float*)d_in[14];
    const float* b2     = (const float*)d_in[15];
    const float* lnf_g  = (const float*)d_in[16];
    const float* lnf_b  = (const float*)d_in[17];
    const float* w_head = (const float*)d_in[18];
    const float* b_head = (const float*)d_in[19];
    float* out = (float*)d_out;

    float *x, *h, *q, *k, *v, *att, *ff;
    cudaGetSymbolAddress((void**)&x,   g_x);
    cudaGetSymbolAddress((void**)&h,   g_h);
    cudaGetSymbolAddress((void**)&q,   g_q);
    cudaGetSymbolAddress((void**)&k,   g_k);
    cudaGetSymbolAddress((void**)&v,   g_v);
    cudaGetSymbolAddress((void**)&att, g_att);
    cudaGetSymbolAddress((void**)&ff,  g_ff);

    embed_kernel<<<(BT * 16) / 256, 256>>>(idx, tok, pos, x);

    dim3 g64(BT / 64, 1);
    for (int l = 0; l < NLAYER; l++) {
        ln_kernel<<<BT / 8, 256>>>(x, h, ln1_g + l * 64, ln1_b + l * 64);
        gemm_kernel<64><<<g64, 64>>>(h, wq + l * 4096, nullptr, nullptr, q, 64, 0);
        gemm_kernel<64><<<g64, 64>>>(h, wk + l * 4096, nullptr, nullptr, k, 64, 0);
        gemm_kernel<64><<<g64, 64>>>(h, wv + l * 4096, nullptr, nullptr, v, 64, 0);
        attn_kernel<<<NBATCH * NH, 256>>>(q, k, v, att);
        gemm_kernel<64><<<g64, 64>>>(att, w_proj + l * 4096, b_proj + l * 64, x, x, 64, 3);
        ln_kernel<<<BT / 8, 256>>>(x, h, ln2_g + l * 64, ln2_b + l * 64);
        gemm_kernel<64><<<dim3(BT / 64, 4), 64>>>(h, w1 + l * 64 * 256, b1 + l * 256,
                                                  nullptr, ff, 256, 5);
        gemm_kernel<256><<<g64, 64>>>(ff, w2 + l * 256 * 64, b2 + l * 64, x, x, 64, 3);
    }
    ln_kernel<<<BT / 8, 256>>>(x, h, lnf_g, lnf_b);
    head_kernel<<<dim3(BT / 64, VOCAB / 64), 256>>>(h, w_head, b_head, out);
}

// round 10
// speedup vs baseline: 1.3396x; 1.3396x over previous
#include <cuda_runtime.h>
#include <cuda_bf16.h>
#include <mma.h>

using namespace nvcuda;

// ---------------- problem constants ----------------
#define NBATCH   64
#define SEQ      256
#define BT       16384      // NBATCH*SEQ
#define C        64
#define NH       8
#define HS       8
#define DFF      256
#define NLAYER   10
#define VOCAB    8000

// ---------------- scratch (static device, no allocs) ----------------
__device__ float g_x  [BT * C];
__device__ float g_q  [BT * C];
__device__ float g_k  [BT * C];
__device__ float g_v  [BT * C];
__device__ float g_att[BT * C];
__device__ float g_ff [BT * DFF];

// ---------------- helpers ----------------
__device__ __forceinline__ float warp_red(float s) {
#pragma unroll
    for (int o = 16; o; o >>= 1) s += __shfl_xor_sync(0xffffffffu, s, o);
    return s;
}

// LayerNorm ROWS_PER_WARP rows per warp (8 warps), write tf32-rounded to smem.
template<int ROWS_PER_WARP>
__device__ __forceinline__ void ln_to_smem(const float* __restrict__ x, int m0,
                                           const float* __restrict__ g,
                                           const float* __restrict__ b,
                                           float* Xs, int ld, int wid, int lane)
{
    float2 gg = *(const float2*)(g + lane * 2);
    float2 bb = *(const float2*)(b + lane * 2);
#pragma unroll
    for (int i = 0; i < ROWS_PER_WARP; i++) {
        int r = wid * ROWS_PER_WARP + i;
        float2 vv = *(const float2*)(x + (size_t)(m0 + r) * C + lane * 2);
        float s  = warp_red(vv.x + vv.y);
        float mu = s * (1.0f / 64.0f);
        float dx = vv.x - mu, dy = vv.y - mu;
        float sq = warp_red(dx * dx + dy * dy);
        float inv = rsqrtf(sq * (1.0f / 64.0f) + 1e-5f);
        Xs[r * ld + lane * 2]     = wmma::__float_to_tf32(dx * inv * gg.x + bb.x);
        Xs[r * ld + lane * 2 + 1] = wmma::__float_to_tf32(dy * inv * gg.y + bb.y);
    }
}

// Load a 64x64 fp32 tile (row stride lds) into smem (row stride ld), tf32-rounded.
// 256 threads.
__device__ __forceinline__ void load_tile_tf32(const float* __restrict__ src, size_t lds,
                                               float* Ds, int ld, int tid)
{
#pragma unroll
    for (int i = 0; i < 4; i++) {
        int u = tid + 256 * i;
        int r = u >> 4, c = (u & 15) << 2;
        float4 w4 = *(const float4*)(src + (size_t)r * lds + c);
        Ds[r * ld + c + 0] = wmma::__float_to_tf32(w4.x);
        Ds[r * ld + c + 1] = wmma::__float_to_tf32(w4.y);
        Ds[r * ld + c + 2] = wmma::__float_to_tf32(w4.z);
        Ds[r * ld + c + 3] = wmma::__float_to_tf32(w4.w);
    }
}

typedef wmma::fragment<wmma::matrix_a, 16, 16, 8, wmma::precision::tf32, wmma::row_major> FragA;
typedef wmma::fragment<wmma::matrix_b, 16, 16, 8, wmma::precision::tf32, wmma::row_major> FragB;
typedef wmma::fragment<wmma::accumulator, 16, 16, 8, float> FragC;

// 64x64x64 mma: warp (wm,wn) owns 16x32 of the 64x64 output; accumulate into c0,c1.
__device__ __forceinline__ void mma_64(const float* Xs, const float* Ws,
                                       int wm, int wn, FragC& c0, FragC& c1)
{
    FragA fa; FragB fb;
#pragma unroll
    for (int kk = 0; kk < 8; kk++) {
        wmma::load_matrix_sync(fa, &Xs[wm * 16 * 72 + kk * 8], 72);
        wmma::load_matrix_sync(fb, &Ws[kk * 8 * 72 + wn * 32], 72);
        wmma::mma_sync(c0, fa, fb, c0);
        wmma::load_matrix_sync(fb, &Ws[kk * 8 * 72 + wn * 32 + 16], 72);
        wmma::mma_sync(c1, fa, fb, c1);
    }
}

// ---------------- embedding ----------------
__global__ void embed_kernel(const int* __restrict__ idx,
                             const float* __restrict__ tok,
                             const float* __restrict__ pos,
                             float* __restrict__ x)
{
    int i = blockIdx.x * blockDim.x + threadIdx.x;
    int r = i >> 4;
    int c = (i & 15) << 2;
    if (r >= BT) return;
    int tk = idx[r];
    float4 a = *(const float4*)(tok + (size_t)tk * C + c);
    float4 p = *(const float4*)(pos + (size_t)(r & (SEQ - 1)) * C + c);
    *(float4*)(x + (size_t)r * C + c) =
        make_float4(a.x + p.x, a.y + p.y, a.z + p.z, a.w + p.w);
}

// ---------------- fused LN1 + QKV ----------------
__global__ __launch_bounds__(256)
void qkv_kernel(const float* __restrict__ x,
                const float* __restrict__ wq, const float* __restrict__ wk,
                const float* __restrict__ wv,
                const float* __restrict__ g, const float* __restrict__ b,
                float* __restrict__ q, float* __restrict__ k, float* __restrict__ v)
{
    __shared__ __align__(16) float Xs[64 * 72];
    __shared__ __align__(16) float Ws[64 * 72];
    int m0 = blockIdx.x * 64;
    int tid = threadIdx.x, wid = tid >> 5, lane = tid & 31;
    int wm = wid >> 1, wn = wid & 1;

    ln_to_smem<8>(x, m0, g, b, Xs, 72, wid, lane);

    const float* Wsel[3] = {wq, wk, wv};
    float*       Osel[3] = {q, k, v};
#pragma unroll
    for (int s = 0; s < 3; s++) {
        __syncthreads();                     // Xs ready / prev Ws reads done
        load_tile_tf32(Wsel[s], 64, Ws, 72, tid);
        __syncthreads();
        FragC c0, c1;
        wmma::fill_fragment(c0, 0.0f);
        wmma::fill_fragment(c1, 0.0f);
        mma_64(Xs, Ws, wm, wn, c0, c1);
        float* op = Osel[s] + (size_t)(m0 + wm * 16) * 64 + wn * 32;
        wmma::store_matrix_sync(op,      c0, 64, wmma::mem_row_major);
        wmma::store_matrix_sync(op + 16, c1, 64, wmma::mem_row_major);
    }
}

// ---------------- attention: one block per (b,h), flash online softmax --------
__global__ __launch_bounds__(256)
void attn_kernel(const float* __restrict__ q, const float* __restrict__ k,
                 const float* __restrict__ v, float* __restrict__ o)
{
    __shared__ float4 ks[SEQ][2];
    __shared__ float4 vs[SEQ][2];
    int b = blockIdx.x >> 3;
    int h = blockIdx.x & 7;
    int t = threadIdx.x;
    size_t base = (size_t)(b * SEQ + t) * C + h * HS;

    ks[t][0] = *(const float4*)(k + base);
    ks[t][1] = *(const float4*)(k + base + 4);
    vs[t][0] = *(const float4*)(v + base);
    vs[t][1] = *(const float4*)(v + base + 4);
    float4 q0 = *(const float4*)(q + base);
    float4 q1 = *(const float4*)(q + base + 4);
    __syncthreads();

    float m = -1e30f, s = 0.0f;
    float o0 = 0, o1 = 0, o2 = 0, o3 = 0, o4 = 0, o5 = 0, o6 = 0, o7 = 0;
    for (int j = 0; j <= t; j++) {
        float4 k0 = ks[j][0], k1 = ks[j][1];
        float sc = q0.x * k0.x + q0.y * k0.y + q0.z * k0.z + q0.w * k0.w
                 + q1.x * k1.x + q1.y * k1.y + q1.z * k1.z + q1.w * k1.w;
        sc *= 0.125f;
        float mn = fmaxf(m, sc);
        float f  = __expf(m - mn);
        float p  = __expf(sc - mn);
        s = s * f + p;
        float4 v0 = vs[j][0], v1 = vs[j][1];
        o0 = o0 * f + p * v0.x;  o1 = o1 * f + p * v0.y;
        o2 = o2 * f + p * v0.z;  o3 = o3 * f + p * v0.w;
        o4 = o4 * f + p * v1.x;  o5 = o5 * f + p * v1.y;
        o6 = o6 * f + p * v1.z;  o7 = o7 * f + p * v1.w;
        m = mn;
    }
    float inv = 1.0f / s;
    *(float4*)(o + base)     = make_float4(o0 * inv, o1 * inv, o2 * inv, o3 * inv);
    *(float4*)(o + base + 4) = make_float4(o4 * inv, o5 * inv, o6 * inv, o7 * inv);
}

// ---------------- proj: x += att @ w_proj + bias ----------------
__global__ __launch_bounds__(256)
void proj_kernel(const float* __restrict__ A, const float* __restrict__ W,
                 const float* __restrict__ bias, float* __restrict__ x)
{
    __shared__ __align__(16) float As[64 * 72];
    __shared__ __align__(16) float Ws[64 * 72];
    int m0 = blockIdx.x * 64;
    int tid = threadIdx.x, wid = tid >> 5;
    int wm = wid >> 1, wn = wid & 1;

    load_tile_tf32(A + (size_t)m0 * 64, 64, As, 72, tid);
    load_tile_tf32(W, 64, Ws, 72, tid);
    __syncthreads();

    FragC c0, c1;
    wmma::fill_fragment(c0, 0.0f);
    wmma::fill_fragment(c1, 0.0f);
    mma_64(As, Ws, wm, wn, c0, c1);
    __syncthreads();
    wmma::store_matrix_sync(&As[wm * 16 * 72 + wn * 32],      c0, 72, wmma::mem_row_major);
    wmma::store_matrix_sync(&As[wm * 16 * 72 + wn * 32 + 16], c1, 72, wmma::mem_row_major);
    __syncthreads();

#pragma unroll
    for (int i = 0; i < 4; i++) {
        int u = tid + 256 * i;
        int r = u >> 4, c = (u & 15) << 2;
        float4 cv = *(float4*)&As[r * 72 + c];
        float4 bb = *(const float4*)(bias + c);
        size_t ro = (size_t)(m0 + r) * 64 + c;
        float4 rr = *(const float4*)(x + ro);
        *(float4*)(x + ro) = make_float4(cv.x + bb.x + rr.x, cv.y + bb.y + rr.y,
                                         cv.z + bb.z + rr.z, cv.w + bb.w + rr.w);
    }
}

// ---------------- fused LN2 + FFN1 + ReLU ----------------
__global__ __launch_bounds__(256)
void ffn1_kernel(const float* __restrict__ x,
                 const float* __restrict__ g, const float* __restrict__ b,
                 const float* __restrict__ W1, const float* __restrict__ b1,
                 float* __restrict__ ff)
{
    __shared__ __align__(16) float Xs[64 * 72];
    __shared__ __align__(16) float Ws[64 * 72];
    int m0 = blockIdx.x * 64;
    int n0 = blockIdx.y * 64;
    int tid = threadIdx.x, wid = tid >> 5, lane = tid & 31;
    int wm = wid >> 1, wn = wid & 1;

    ln_to_smem<8>(x, m0, g, b, Xs, 72, wid, lane);
    load_tile_tf32(W1 + n0, DFF, Ws, 72, tid);
    __syncthreads();

    FragC c0, c1;
    wmma::fill_fragment(c0, 0.0f);
    wmma::fill_fragment(c1, 0.0f);
    mma_64(Xs, Ws, wm, wn, c0, c1);
    __syncthreads();
    wmma::store_matrix_sync(&Xs[wm * 16 * 72 + wn * 32],      c0, 72, wmma::mem_row_major);
    wmma::store_matrix_sync(&Xs[wm * 16 * 72 + wn * 32 + 16], c1, 72, wmma::mem_row_major);
    __syncthreads();

#pragma unroll
    for (int i = 0; i < 4; i++) {
        int u = tid + 256 * i;
        int r = u >> 4, c = (u & 15) << 2;
        float4 cv = *(float4*)&Xs[r * 72 + c];
        float4 bb = *(const float4*)(b1 + n0 + c);
        *(float4*)(ff + (size_t)(m0 + r) * DFF + n0 + c) =
            make_float4(fmaxf(cv.x + bb.x, 0.0f), fmaxf(cv.y + bb.y, 0.0f),
                        fmaxf(cv.z + bb.z, 0.0f), fmaxf(cv.w + bb.w, 0.0f));
    }
}

// ---------------- FFN2: x += ff @ w2 + bias (K=256) ----------------
__global__ __launch_bounds__(256)
void ffn2_kernel(const float* __restrict__ ff, const float* __restrict__ W2,
                 const float* __restrict__ b2, float* __restrict__ x)
{
    __shared__ __align__(16) float As[64 * 72];
    __shared__ __align__(16) float Ws[64 * 72];
    int m0 = blockIdx.x * 64;
    int tid = threadIdx.x, wid = tid >> 5;
    int wm = wid >> 1, wn = wid & 1;

    FragC c0, c1;
    wmma::fill_fragment(c0, 0.0f);
    wmma::fill_fragment(c1, 0.0f);

#pragma unroll
    for (int kc = 0; kc < 4; kc++) {
        __syncthreads();                     // prev-chunk reads done
        load_tile_tf32(ff + (size_t)m0 * DFF + kc * 64, DFF, As, 72, tid);
        load_tile_tf32(W2 + (size_t)kc * 64 * 64, 64, Ws, 72, tid);
        __syncthreads();
        mma_64(As, Ws, wm, wn, c0, c1);
    }
    __syncthreads();
    wmma::store_matrix_sync(&As[wm * 16 * 72 + wn * 32],      c0, 72, wmma::mem_row_major);
    wmma::store_matrix_sync(&As[wm * 16 * 72 + wn * 32 + 16], c1, 72, wmma::mem_row_major);
    __syncthreads();

#pragma unroll
    for (int i = 0; i < 4; i++) {
        int u = tid + 256 * i;
        int r = u >> 4, c = (u & 15) << 2;
        float4 cv = *(float4*)&As[r * 72 + c];
        float4 bb = *(const float4*)(b2 + c);
        size_t ro = (size_t)(m0 + r) * 64 + c;
        float4 rr = *(const float4*)(x + ro);
        *(float4*)(x + ro) = make_float4(cv.x + bb.x + rr.x, cv.y + bb.y + rr.y,
                                         cv.z + bb.z + rr.z, cv.w + bb.w + rr.w);
    }
}

// ---------------- fused LNf + LM head: M-tile 128, N-tile 64 ----------------
__global__ __launch_bounds__(256)
void head_kernel(const float* __restrict__ x,
                 const float* __restrict__ g, const float* __restrict__ b,
                 const float* __restrict__ W, const float* __restrict__ bias,
                 float* __restrict__ out)
{
    __shared__ __align__(16) float Xs[128 * 64];   // 32KB
    __shared__ __align__(16) float Ws[64 * 64];    // 16KB (total 48KB exactly)
    int m0 = blockIdx.x * 128;
    int n0 = blockIdx.y * 64;
    int tid = threadIdx.x, wid = tid >> 5, lane = tid & 31;

    ln_to_smem<16>(x, m0, g, b, Xs, 64, wid, lane);
    load_tile_tf32(W + n0, VOCAB, Ws, 64, tid);
    __syncthreads();

    FragA fa; FragB fb;
    FragC acc[4];
#pragma unroll
    for (int nt = 0; nt < 4; nt++) wmma::fill_fragment(acc[nt], 0.0f);

#pragma unroll
    for (int kk = 0; kk < 8; kk++) {
        wmma::load_matrix_sync(fa, &Xs[wid * 16 * 64 + kk * 8], 64);
#pragma unroll
        for (int nt = 0; nt < 4; nt++) {
            wmma::load_matrix_sync(fb, &Ws[kk * 8 * 64 + nt * 16], 64);
            wmma::mma_sync(acc[nt], fa, fb, acc[nt]);
        }
    }
    __syncthreads();
#pragma unroll
    for (int nt = 0; nt < 4; nt++)
        wmma::store_matrix_sync(&Xs[wid * 16 * 64 + nt * 16], acc[nt], 64,
                                wmma::mem_row_major);
    __syncthreads();

#pragma unroll
    for (int i = 0; i < 8; i++) {
        int u = tid + 256 * i;
        int r = u >> 4, c = (u & 15) << 2;
        float4 cv = *(float4*)&Xs[r * 64 + c];
        float4 bb = *(const float4*)(bias + n0 + c);
        *(float4*)(out + (size_t)(m0 + r) * VOCAB + n0 + c) =
            make_float4(cv.x + bb.x, cv.y + bb.y, cv.z + bb.z, cv.w + bb.w);
    }
}

// ---------------- launch ----------------
extern "C" void kernel_launch(void* const* d_in, const int* in_sizes, int n_in,
                              void* d_out, int out_size)
{
    const int*   idx    = (const int*)  d_in[0];
    const float* tok    = (const float*)d_in[1];
    const float* pos    = (const float*)d_in[2];
    const float* wq     = (const float*)d_in[3];
    const float* wk     = (const float*)d_in[4];
    const float* wv     = (const float*)d_in[5];
    const float* w_proj = (const float*)d_in[6];
    const float* b_proj = (const float*)d_in[7];
    const float* ln1_g  = (const float*)d_in[8];
    const float* ln1_b  = (const float*)d_in[9];
    const float* ln2_g  = (const float*)d_in[10];
    const float* ln2_b  = (const float*)d_in[11];
    const float* w1     = (const float*)d_in[12];
    const float* b1     = (const float*)d_in[13];
    const float* w2     = (const float*)d_in[14];
    const float* b2     = (const float*)d_in[15];
    const float* lnf_g  = (const float*)d_in[16];
    const float* lnf_b  = (const float*)d_in[17];
    const float* w_head = (const float*)d_in[18];
    const float* b_head = (const float*)d_in[19];
    float* out = (float*)d_out;

    float *x, *q, *k, *v, *att, *ff;
    cudaGetSymbolAddress((void**)&x,   g_x);
    cudaGetSymbolAddress((void**)&q,   g_q);
    cudaGetSymbolAddress((void**)&k,   g_k);
    cudaGetSymbolAddress((void**)&v,   g_v);
    cudaGetSymbolAddress((void**)&att, g_att);
    cudaGetSymbolAddress((void**)&ff,  g_ff);

    embed_kernel<<<(BT * 16) / 256, 256>>>(idx, tok, pos, x);

    for (int l = 0; l < NLAYER; l++) {
        qkv_kernel<<<BT / 64, 256>>>(x, wq + l * 4096, wk + l * 4096, wv + l * 4096,
                                     ln1_g + l * 64, ln1_b + l * 64, q, k, v);
        attn_kernel<<<NBATCH * NH, 256>>>(q, k, v, att);
        proj_kernel<<<BT / 64, 256>>>(att, w_proj + l * 4096, b_proj + l * 64, x);
        ffn1_kernel<<<dim3(BT / 64, 4), 256>>>(x, ln2_g + l * 64, ln2_b + l * 64,
                                               w1 + l * 64 * 256, b1 + l * 256, ff);
        ffn2_kernel<<<BT / 64, 256>>>(ff, w2 + l * 256 * 64, b2 + l * 64, x);
    }
    head_kernel<<<dim3(BT / 128, VOCAB / 64), 256>>>(x, lnf_g, lnf_b,
                                                     w_head, b_head, out);
}

// round 12
// speedup vs baseline: 1.3983x; 1.0439x over previous
#include <cuda_runtime.h>
#include <cuda_bf16.h>
#include <mma.h>

using namespace nvcuda;

// ---------------- problem constants ----------------
#define NBATCH   64
#define SEQ      256
#define BT       16384
#define C        64
#define NH       8
#define HS       8
#define DFF      256
#define NLAYER   10
#define VOCAB    8000

// ---------------- scratch (static device, no allocs) ----------------
__device__ float g_x  [BT * C];     // residual stream (fp32)
__device__ float g_h  [BT * C];     // current LN output (tf32-rounded)
__device__ float g_q  [BT * C];
__device__ float g_k  [BT * C];
__device__ float g_v  [BT * C];
__device__ float g_att[BT * C];
__device__ float g_ff [BT * DFF];

// ---------------- helpers ----------------
__device__ __forceinline__ float warp_red(float s) {
#pragma unroll
    for (int o = 16; o; o >>= 1) s += __shfl_xor_sync(0xffffffffu, s, o);
    return s;
}

typedef wmma::fragment<wmma::matrix_a, 16, 16, 8, wmma::precision::tf32, wmma::row_major> FragA;
typedef wmma::fragment<wmma::matrix_b, 16, 16, 8, wmma::precision::tf32, wmma::row_major> FragB;
typedef wmma::fragment<wmma::accumulator, 16, 16, 8, float> FragC;

// 64x64 fp32 tile (row stride lds) -> smem (stride ld), tf32-rounded. 256 thr.
__device__ __forceinline__ void load_tile_tf32(const float* __restrict__ src, size_t lds,
                                               float* Ds, int ld, int tid)
{
#pragma unroll
    for (int i = 0; i < 4; i++) {
        int u = tid + 256 * i;
        int r = u >> 4, c = (u & 15) << 2;
        float4 w4 = *(const float4*)(src + (size_t)r * lds + c);
        Ds[r * ld + c + 0] = wmma::__float_to_tf32(w4.x);
        Ds[r * ld + c + 1] = wmma::__float_to_tf32(w4.y);
        Ds[r * ld + c + 2] = wmma::__float_to_tf32(w4.z);
        Ds[r * ld + c + 3] = wmma::__float_to_tf32(w4.w);
    }
}

// 64x64 plain copy (values already tf32-rounded). 256 threads.
__device__ __forceinline__ void load_tile_raw(const float* __restrict__ src, size_t lds,
                                              float* Ds, int ld, int tid)
{
#pragma unroll
    for (int i = 0; i < 4; i++) {
        int u = tid + 256 * i;
        int r = u >> 4, c = (u & 15) << 2;
        *(float4*)&Ds[r * ld + c] = *(const float4*)(src + (size_t)r * lds + c);
    }
}

// 64x64x64 mma: warp (wm,wn) owns 16x32; accumulate into c0,c1.
__device__ __forceinline__ void mma_64(const float* Xs, int lda, const float* Ws, int ldb,
                                       int wm, int wn, FragC& c0, FragC& c1)
{
    FragA fa; FragB fb;
#pragma unroll
    for (int kk = 0; kk < 8; kk++) {
        wmma::load_matrix_sync(fa, &Xs[wm * 16 * lda + kk * 8], lda);
        wmma::load_matrix_sync(fb, &Ws[kk * 8 * ldb + wn * 32], ldb);
        wmma::mma_sync(c0, fa, fb, c0);
        wmma::load_matrix_sync(fb, &Ws[kk * 8 * ldb + wn * 32 + 16], ldb);
        wmma::mma_sync(c1, fa, fb, c1);
    }
}

// LN of 64 rows sitting in smem S (stride 72, 64 valid cols) -> h (tf32-rounded).
// 8 warps x 8 rows.
__device__ __forceinline__ void ln_from_smem(const float* S, int m0,
                                             const float* __restrict__ g,
                                             const float* __restrict__ b,
                                             float* __restrict__ h, int wid, int lane)
{
    float2 gg = *(const float2*)(g + lane * 2);
    float2 bb = *(const float2*)(b + lane * 2);
#pragma unroll
    for (int i = 0; i < 8; i++) {
        int r = wid * 8 + i;
        float vx = S[r * 72 + lane * 2], vy = S[r * 72 + lane * 2 + 1];
        float s  = warp_red(vx + vy);
        float mu = s * (1.0f / 64.0f);
        float dx = vx - mu, dy = vy - mu;
        float sq = warp_red(dx * dx + dy * dy);
        float inv = rsqrtf(sq * (1.0f / 64.0f) + 1e-5f);
        float2 o2 = make_float2(wmma::__float_to_tf32(dx * inv * gg.x + bb.x),
                                wmma::__float_to_tf32(dy * inv * gg.y + bb.y));
        *(float2*)(h + (size_t)(m0 + r) * C + lane * 2) = o2;
    }
}

// ---------------- embedding + LN1(layer0) ----------------
__global__ __launch_bounds__(256)
void embed_ln_kernel(const int* __restrict__ idx,
                     const float* __restrict__ tok,
                     const float* __restrict__ pos,
                     const float* __restrict__ g, const float* __restrict__ b,
                     float* __restrict__ x, float* __restrict__ h)
{
    int m0 = blockIdx.x * 64;
    int wid = threadIdx.x >> 5, lane = threadIdx.x & 31;
    float2 gg = *(const float2*)(g + lane * 2);
    float2 bb = *(const float2*)(b + lane * 2);
#pragma unroll
    for (int i = 0; i < 8; i++) {
        int r = m0 + wid * 8 + i;
        int tk = idx[r];
        float2 tv = *(const float2*)(tok + (size_t)tk * C + lane * 2);
        float2 pv = *(const float2*)(pos + (size_t)(r & (SEQ - 1)) * C + lane * 2);
        float vx = tv.x + pv.x, vy = tv.y + pv.y;
        *(float2*)(x + (size_t)r * C + lane * 2) = make_float2(vx, vy);
        float s  = warp_red(vx + vy);
        float mu = s * (1.0f / 64.0f);
        float dx = vx - mu, dy = vy - mu;
        float sq = warp_red(dx * dx + dy * dy);
        float inv = rsqrtf(sq * (1.0f / 64.0f) + 1e-5f);
        *(float2*)(h + (size_t)r * C + lane * 2) =
            make_float2(wmma::__float_to_tf32(dx * inv * gg.x + bb.x),
                        wmma::__float_to_tf32(dy * inv * gg.y + bb.y));
    }
}

// ---------------- QKV: h @ {wq,wk,wv}; all W preloaded, one sync ----------------
__global__ __launch_bounds__(256)
void qkv_kernel(const float* __restrict__ h,
                const float* __restrict__ wq, const float* __restrict__ wk,
                const float* __restrict__ wv,
                float* __restrict__ q, float* __restrict__ k, float* __restrict__ v)
{
    extern __shared__ __align__(16) float sm[];
    float* Xs = sm;                 // 64*72
    float* Ws = sm + 64 * 72;       // 3 * 64*72
    int m0 = blockIdx.x * 64;
    int tid = threadIdx.x, wid = tid >> 5;
    int wm = wid >> 1, wn = wid & 1;

    load_tile_raw(h + (size_t)m0 * C, C, Xs, 72, tid);
    load_tile_tf32(wq, 64, Ws,             72, tid);
    load_tile_tf32(wk, 64, Ws + 64 * 72,   72, tid);
    load_tile_tf32(wv, 64, Ws + 2 * 64 * 72, 72, tid);
    __syncthreads();

    float* Osel[3] = {q, k, v};
#pragma unroll
    for (int s = 0; s < 3; s++) {
        FragC c0, c1;
        wmma::fill_fragment(c0, 0.0f);
        wmma::fill_fragment(c1, 0.0f);
        mma_64(Xs, 72, Ws + s * 64 * 72, 72, wm, wn, c0, c1);
        float* op = Osel[s] + (size_t)(m0 + wm * 16) * C + wn * 32;
        wmma::store_matrix_sync(op,      c0, C, wmma::mem_row_major);
        wmma::store_matrix_sync(op + 16, c1, C, wmma::mem_row_major);
    }
}

// ---------------- attention: max-free online softmax ----------------
__global__ __launch_bounds__(256)
void attn_kernel(const float* __restrict__ q, const float* __restrict__ k,
                 const float* __restrict__ v, float* __restrict__ o)
{
    __shared__ float4 ks[SEQ][2];
    __shared__ float4 vs[SEQ][2];
    int b = blockIdx.x >> 3;
    int h = blockIdx.x & 7;
    int t = threadIdx.x;
    size_t base = (size_t)(b * SEQ + t) * C + h * HS;

    ks[t][0] = *(const float4*)(k + base);
    ks[t][1] = *(const float4*)(k + base + 4);
    vs[t][0] = *(const float4*)(v + base);
    vs[t][1] = *(const float4*)(v + base + 4);
    float4 q0 = *(const float4*)(q + base);
    float4 q1 = *(const float4*)(q + base + 4);
    __syncthreads();

    float s = 0.0f;
    float o0 = 0, o1 = 0, o2 = 0, o3 = 0, o4 = 0, o5 = 0, o6 = 0, o7 = 0;
    for (int j = 0; j <= t; j++) {
        float4 k0 = ks[j][0], k1 = ks[j][1];
        float sc = q0.x * k0.x + q0.y * k0.y + q0.z * k0.z + q0.w * k0.w
                 + q1.x * k1.x + q1.y * k1.y + q1.z * k1.z + q1.w * k1.w;
        float p = __expf(sc * 0.125f);
        s += p;
        float4 v0 = vs[j][0], v1 = vs[j][1];
        o0 += p * v0.x;  o1 += p * v0.y;  o2 += p * v0.z;  o3 += p * v0.w;
        o4 += p * v1.x;  o5 += p * v1.y;  o6 += p * v1.z;  o7 += p * v1.w;
    }
    float inv = 1.0f / s;
    *(float4*)(o + base)     = make_float4(o0 * inv, o1 * inv, o2 * inv, o3 * inv);
    *(float4*)(o + base + 4) = make_float4(o4 * inv, o5 * inv, o6 * inv, o7 * inv);
}

// ---------------- proj: x += att @ Wp + bias, then h = LN2(x) ----------------
__global__ __launch_bounds__(256)
void proj_kernel(const float* __restrict__ A, const float* __restrict__ W,
                 const float* __restrict__ bias, float* __restrict__ x,
                 const float* __restrict__ ln_g, const float* __restrict__ ln_b,
                 float* __restrict__ h)
{
    __shared__ __align__(16) float As[64 * 72];
    __shared__ __align__(16) float Ws[64 * 72];
    int m0 = blockIdx.x * 64;
    int tid = threadIdx.x, wid = tid >> 5, lane = tid & 31;
    int wm = wid >> 1, wn = wid & 1;

    load_tile_tf32(A + (size_t)m0 * C, C, As, 72, tid);
    load_tile_tf32(W, 64, Ws, 72, tid);
    __syncthreads();

    FragC c0, c1;
    wmma::fill_fragment(c0, 0.0f);
    wmma::fill_fragment(c1, 0.0f);
    mma_64(As, 72, Ws, 72, wm, wn, c0, c1);
    __syncthreads();
    wmma::store_matrix_sync(&Ws[wm * 16 * 72 + wn * 32],      c0, 72, wmma::mem_row_major);
    wmma::store_matrix_sync(&Ws[wm * 16 * 72 + wn * 32 + 16], c1, 72, wmma::mem_row_major);
    __syncthreads();

#pragma unroll
    for (int i = 0; i < 4; i++) {
        int u = tid + 256 * i;
        int r = u >> 4, c = (u & 15) << 2;
        float4 cv = *(float4*)&Ws[r * 72 + c];
        float4 bb = *(const float4*)(bias + c);
        size_t ro = (size_t)(m0 + r) * C + c;
        float4 rr = *(const float4*)(x + ro);
        float4 nx = make_float4(cv.x + bb.x + rr.x, cv.y + bb.y + rr.y,
                                cv.z + bb.z + rr.z, cv.w + bb.w + rr.w);
        *(float4*)(x + ro) = nx;
        *(float4*)&As[r * 72 + c] = nx;
    }
    __syncthreads();
    ln_from_smem(As, m0, ln_g, ln_b, h, wid, lane);
}

// ---------------- FFN1: ff = relu(h @ W1 + b1); full W1 preloaded ----------------
__global__ __launch_bounds__(256)
void ffn1_kernel(const float* __restrict__ h, const float* __restrict__ W1,
                 const float* __restrict__ b1, float* __restrict__ ff)
{
    extern __shared__ __align__(16) float sm[];
    float* Xs  = sm;                 // 64*72
    float* W1s = sm + 64 * 72;       // 64*264
    int m0 = blockIdx.x * 64;
    int tid = threadIdx.x, wid = tid >> 5;

    load_tile_raw(h + (size_t)m0 * C, C, Xs, 72, tid);
#pragma unroll
    for (int i = 0; i < 16; i++) {
        int u = tid + 256 * i;
        int r = u >> 6, c4 = u & 63;
        float4 w4 = *(const float4*)(W1 + (size_t)r * DFF + c4 * 4);
        float* d = &W1s[r * 264 + c4 * 4];
        d[0] = wmma::__float_to_tf32(w4.x);
        d[1] = wmma::__float_to_tf32(w4.y);
        d[2] = wmma::__float_to_tf32(w4.z);
        d[3] = wmma::__float_to_tf32(w4.w);
    }
    __syncthreads();

    int m  = wid & 3;
    int nb = (wid >> 2) * 8;
    FragC acc[8];
#pragma unroll
    for (int j = 0; j < 8; j++) wmma::fill_fragment(acc[j], 0.0f);
    FragA fa; FragB fb;
#pragma unroll
    for (int kk = 0; kk < 8; kk++) {
        wmma::load_matrix_sync(fa, &Xs[m * 16 * 72 + kk * 8], 72);
#pragma unroll
        for (int j = 0; j < 8; j++) {
            wmma::load_matrix_sync(fb, &W1s[kk * 8 * 264 + (nb + j) * 16], 264);
            wmma::mma_sync(acc[j], fa, fb, acc[j]);
        }
    }
    __syncthreads();
#pragma unroll
    for (int j = 0; j < 8; j++)
        wmma::store_matrix_sync(&W1s[m * 16 * 264 + (nb + j) * 16], acc[j], 264,
                                wmma::mem_row_major);
    __syncthreads();

#pragma unroll
    for (int i = 0; i < 16; i++) {
        int u = tid + 256 * i;
        int r = u >> 6, c4 = u & 63;
        float4 cv = *(float4*)&W1s[r * 264 + c4 * 4];
        float4 bb = *(const float4*)(b1 + c4 * 4);
        *(float4*)(ff + (size_t)(m0 + r) * DFF + c4 * 4) =
            make_float4(wmma::__float_to_tf32(fmaxf(cv.x + bb.x, 0.0f)),
                        wmma::__float_to_tf32(fmaxf(cv.y + bb.y, 0.0f)),
                        wmma::__float_to_tf32(fmaxf(cv.z + bb.z, 0.0f)),
                        wmma::__float_to_tf32(fmaxf(cv.w + bb.w, 0.0f)));
    }
}

// ---------------- FFN2: x += ff @ W2 + b2, then h = LN_next(x) ----------------
__global__ __launch_bounds__(256)
void ffn2_kernel(const float* __restrict__ ff, const float* __restrict__ W2,
                 const float* __restrict__ b2, float* __restrict__ x,
                 const float* __restrict__ ln_g, const float* __restrict__ ln_b,
                 float* __restrict__ h)
{
    extern __shared__ __align__(16) float sm[];
    float* As  = sm;                 // 64*264 (A; later 64x72 C/x staging)
    float* Ws2 = sm + 64 * 264;      // 256*72
    int m0 = blockIdx.x * 64;
    int tid = threadIdx.x, wid = tid >> 5, lane = tid & 31;
    int wm = wid >> 1, wn = wid & 1;

#pragma unroll
    for (int i = 0; i < 16; i++) {                       // A: already tf32-rounded
        int u = tid + 256 * i;
        int r = u >> 6, c4 = u & 63;
        *(float4*)&As[r * 264 + c4 * 4] =
            *(const float4*)(ff + (size_t)(m0 + r) * DFF + c4 * 4);
    }
#pragma unroll
    for (int i = 0; i < 16; i++) {                       // W2 [256][64]
        int u = tid + 256 * i;
        int r = u >> 4, c = (u & 15) << 2;
        float4 w4 = *(const float4*)(W2 + (size_t)r * C + c);
        float* d = &Ws2[r * 72 + c];
        d[0] = wmma::__float_to_tf32(w4.x);
        d[1] = wmma::__float_to_tf32(w4.y);
        d[2] = wmma::__float_to_tf32(w4.z);
        d[3] = wmma::__float_to_tf32(w4.w);
    }
    __syncthreads();

    FragC c0, c1;
    wmma::fill_fragment(c0, 0.0f);
    wmma::fill_fragment(c1, 0.0f);
    FragA fa; FragB fb;
#pragma unroll
    for (int kk = 0; kk < 32; kk++) {
        wmma::load_matrix_sync(fa, &As[wm * 16 * 264 + kk * 8], 264);
        wmma::load_matrix_sync(fb, &Ws2[kk * 8 * 72 + wn * 32], 72);
        wmma::mma_sync(c0, fa, fb, c0);
        wmma::load_matrix_sync(fb, &Ws2[kk * 8 * 72 + wn * 32 + 16], 72);
        wmma::mma_sync(c1, fa, fb, c1);
    }
    __syncthreads();
    wmma::store_matrix_sync(&As[wm * 16 * 72 + wn * 32],      c0, 72, wmma::mem_row_major);
    wmma::store_matrix_sync(&As[wm * 16 * 72 + wn * 32 + 16], c1, 72, wmma::mem_row_major);
    __syncthreads();

#pragma unroll
    for (int i = 0; i < 4; i++) {
        int u = tid + 256 * i;
        int r = u >> 4, c = (u & 15) << 2;
        float4 cv = *(float4*)&As[r * 72 + c];
        float4 bb = *(const float4*)(b2 + c);
        size_t ro = (size_t)(m0 + r) * C + c;
        float4 rr = *(const float4*)(x + ro);
        float4 nx = make_float4(cv.x + bb.x + rr.x, cv.y + bb.y + rr.y,
                                cv.z + bb.z + rr.z, cv.w + bb.w + rr.w);
        *(float4*)(x + ro) = nx;
        *(float4*)&As[r * 72 + c] = nx;
    }
    __syncthreads();
    ln_from_smem(As, m0, ln_g, ln_b, h, wid, lane);
}

// ---------------- LM head: grid (128,5); A-frags in regs; 25 N-tiles/block ------
__global__ __launch_bounds__(256)
void head_kernel(const float* __restrict__ h, const float* __restrict__ W,
                 const float* __restrict__ bias, float* __restrict__ out)
{
    extern __shared__ __align__(16) float sm[];
    float* Xs = sm;                  // 128*72  (A; later C staging)
    float* Ws = sm + 128 * 72;       // 64*72
    int m0 = blockIdx.x * 128;
    int tid = threadIdx.x, wid = tid >> 5;

#pragma unroll
    for (int i = 0; i < 8; i++) {                        // h already tf32-rounded
        int u = tid + 256 * i;
        int r = u >> 4, c = (u & 15) << 2;
        *(float4*)&Xs[r * 72 + c] = *(const float4*)(h + (size_t)(m0 + r) * C + c);
    }
    __syncthreads();

    FragA fa[8];
#pragma unroll
    for (int kk = 0; kk < 8; kk++)
        wmma::load_matrix_sync(fa[kk], &Xs[wid * 16 * 72 + kk * 8], 72);

    for (int i = 0; i < 25; i++) {
        int n0 = (blockIdx.y * 25 + i) * 64;
        __syncthreads();                                 // prev epilogue/Cs reads done
#pragma unroll
        for (int j = 0; j < 4; j++) {                    // load W tile
            int u = tid + 256 * j;
            int r = u >> 4, c = (u & 15) << 2;
            float4 w4 = *(const float4*)(W + (size_t)r * VOCAB + n0 + c);
            float* d = &Ws[r * 72 + c];
            d[0] = wmma::__float_to_tf32(w4.x);
            d[1] = wmma::__float_to_tf32(w4.y);
            d[2] = wmma::__float_to_tf32(w4.z);
            d[3] = wmma::__float_to_tf32(w4.w);
        }
        __syncthreads();

        FragC acc[4];
#pragma unroll
        for (int nt = 0; nt < 4; nt++) wmma::fill_fragment(acc[nt], 0.0f);
        FragB fb;
#pragma unroll
        for (int kk = 0; kk < 8; kk++)
#pragma unroll
            for (int nt = 0; nt < 4; nt++) {
                wmma::load_matrix_sync(fb, &Ws[kk * 8 * 72 + nt * 16], 72);
                wmma::mma_sync(acc[nt], fa[kk], fb, acc[nt]);
            }
        __syncthreads();                                 // Ws reads done; Xs fa done
#pragma unroll
        for (int nt = 0; nt < 4; nt++)
            wmma::store_matrix_sync(&Xs[wid * 16 * 72 + nt * 16], acc[nt], 72,
                                    wmma::mem_row_major);
        __syncthreads();

#pragma unroll
        for (int j = 0; j < 8; j++) {
            int u = tid + 256 * j;
            int r = u >> 4, c = (u & 15) << 2;
            float4 cv = *(float4*)&Xs[r * 72 + c];
            float4 bb = *(const float4*)(bias + n0 + c);
            *(float4*)(out + (size_t)(m0 + r) * VOCAB + n0 + c) =
                make_float4(cv.x + bb.x, cv.y + bb.y, cv.z + bb.z, cv.w + bb.w);
        }
    }
}

// ---------------- launch ----------------
extern "C" void kernel_launch(void* const* d_in, const int* in_sizes, int n_in,
                              void* d_out, int out_size)
{
    const int*   idx    = (const int*)  d_in[0];
    const float* tok    = (const float*)d_in[1];
    const float* pos    = (const float*)d_in[2];
    const float* wq     = (const float*)d_in[3];
    const float* wk     = (const float*)d_in[4];
    const float* wv     = (const float*)d_in[5];
    const float* w_proj = (const float*)d_in[6];
    const float* b_proj = (const float*)d_in[7];
    const float* ln1_g  = (const float*)d_in[8];
    const float* ln1_b  = (const float*)d_in[9];
    const float* ln2_g  = (const float*)d_in[10];
    const float* ln2_b  = (const float*)d_in[11];
    const float* w1     = (const float*)d_in[12];
    const float* b1     = (const float*)d_in[13];
    const float* w2     = (const float*)d_in[14];
    const float* b2     = (const float*)d_in[15];
    const float* lnf_g  = (const float*)d_in[16];
    const float* lnf_b  = (const float*)d_in[17];
    const float* w_head = (const float*)d_in[18];
    const float* b_head = (const float*)d_in[19];
    float* out = (float*)d_out;

    float *x, *h, *q, *k, *v, *att, *ff;
    cudaGetSymbolAddress((void**)&x,   g_x);
    cudaGetSymbolAddress((void**)&h,   g_h);
    cudaGetSymbolAddress((void**)&q,   g_q);
    cudaGetSymbolAddress((void**)&k,   g_k);
    cudaGetSymbolAddress((void**)&v,   g_v);
    cudaGetSymbolAddress((void**)&att, g_att);
    cudaGetSymbolAddress((void**)&ff,  g_ff);

    const int QKV_SMEM  = (64 * 72 + 3 * 64 * 72) * 4;   // 73,728
    const int FFN1_SMEM = (64 * 72 + 64 * 264) * 4;      // 86,016
    const int FFN2_SMEM = (64 * 264 + 256 * 72) * 4;     // 141,312
    const int HEAD_SMEM = (128 * 72 + 64 * 72) * 4;      // 55,296
    cudaFuncSetAttribute(qkv_kernel,  cudaFuncAttributeMaxDynamicSharedMemorySize, QKV_SMEM);
    cudaFuncSetAttribute(ffn1_kernel, cudaFuncAttributeMaxDynamicSharedMemorySize, FFN1_SMEM);
    cudaFuncSetAttribute(ffn2_kernel, cudaFuncAttributeMaxDynamicSharedMemorySize, FFN2_SMEM);
    cudaFuncSetAttribute(head_kernel, cudaFuncAttributeMaxDynamicSharedMemorySize, HEAD_SMEM);

    embed_ln_kernel<<<BT / 64, 256>>>(idx, tok, pos, ln1_g, ln1_b, x, h);

    for (int l = 0; l < NLAYER; l++) {
        qkv_kernel<<<BT / 64, 256, QKV_SMEM>>>(h, wq + l * 4096, wk + l * 4096,
                                               wv + l * 4096, q, k, v);
        attn_kernel<<<NBATCH * NH, 256>>>(q, k, v, att);
        proj_kernel<<<BT / 64, 256>>>(att, w_proj + l * 4096, b_proj + l * 64, x,
                                      ln2_g + l * 64, ln2_b + l * 64, h);
        ffn1_kernel<<<BT / 64, 256, FFN1_SMEM>>>(h, w1 + l * 64 * 256, b1 + l * 256, ff);
        const float* gn = (l < NLAYER - 1) ? (ln1_g + (l + 1) * 64) : lnf_g;
        const float* bn = (l < NLAYER - 1) ? (ln1_b + (l + 1) * 64) : lnf_b;
        ffn2_kernel<<<BT / 64, 256, FFN2_SMEM>>>(ff, w2 + l * 256 * 64, b2 + l * 64,
                                                 x, gn, bn, h);
    }
    head_kernel<<<dim3(BT / 128, 5), 256, HEAD_SMEM>>>(h, w_head, b_head, out);
}

// round 13
// speedup vs baseline: 1.6751x; 1.1980x over previous
#include <cuda_runtime.h>
#include <cuda_bf16.h>
#include <mma.h>

using namespace nvcuda;

// ---------------- problem constants ----------------
#define NBATCH   64
#define SEQ      256
#define BT       16384
#define C        64
#define NH       8
#define HS       8
#define DFF      256
#define NLAYER   10
#define VOCAB    8000

// ---------------- scratch (static device, no allocs) ----------------
__device__ float g_x  [BT * C];     // residual stream (fp32)
__device__ float g_h  [BT * C];     // LN output feeding qkv / head (tf32-rounded)
__device__ float g_q  [BT * C];
__device__ float g_k  [BT * C];
__device__ float g_v  [BT * C];
__device__ float g_att[BT * C];
__device__ float g_ff [BT * DFF];

// ---------------- helpers ----------------
__device__ __forceinline__ float warp_red(float s) {
#pragma unroll
    for (int o = 16; o; o >>= 1) s += __shfl_xor_sync(0xffffffffu, s, o);
    return s;
}

typedef wmma::fragment<wmma::matrix_a, 16, 16, 8, wmma::precision::tf32, wmma::row_major> FragA;
typedef wmma::fragment<wmma::matrix_b, 16, 16, 8, wmma::precision::tf32, wmma::row_major> FragB;
typedef wmma::fragment<wmma::accumulator, 16, 16, 8, float> FragC;

// 64x64 fp32 tile (row stride lds) -> smem (stride ld), tf32-rounded. 256 thr.
__device__ __forceinline__ void load_tile_tf32(const float* __restrict__ src, size_t lds,
                                               float* Ds, int ld, int tid)
{
#pragma unroll
    for (int i = 0; i < 4; i++) {
        int u = tid + 256 * i;
        int r = u >> 4, c = (u & 15) << 2;
        float4 w4 = *(const float4*)(src + (size_t)r * lds + c);
        Ds[r * ld + c + 0] = wmma::__float_to_tf32(w4.x);
        Ds[r * ld + c + 1] = wmma::__float_to_tf32(w4.y);
        Ds[r * ld + c + 2] = wmma::__float_to_tf32(w4.z);
        Ds[r * ld + c + 3] = wmma::__float_to_tf32(w4.w);
    }
}

// 64x64 plain copy (values already tf32-rounded). 256 threads.
__device__ __forceinline__ void load_tile_raw(const float* __restrict__ src, size_t lds,
                                              float* Ds, int ld, int tid)
{
#pragma unroll
    for (int i = 0; i < 4; i++) {
        int u = tid + 256 * i;
        int r = u >> 4, c = (u & 15) << 2;
        *(float4*)&Ds[r * ld + c] = *(const float4*)(src + (size_t)r * lds + c);
    }
}

// 64x64x64 mma: warp (wm,wn) owns 16x32; accumulate into c0,c1.
__device__ __forceinline__ void mma_64(const float* Xs, int lda, const float* Ws, int ldb,
                                       int wm, int wn, FragC& c0, FragC& c1)
{
    FragA fa; FragB fb;
#pragma unroll
    for (int kk = 0; kk < 8; kk++) {
        wmma::load_matrix_sync(fa, &Xs[wm * 16 * lda + kk * 8], lda);
        wmma::load_matrix_sync(fb, &Ws[kk * 8 * ldb + wn * 32], ldb);
        wmma::mma_sync(c0, fa, fb, c0);
        wmma::load_matrix_sync(fb, &Ws[kk * 8 * ldb + wn * 32 + 16], ldb);
        wmma::mma_sync(c1, fa, fb, c1);
    }
}

// LN of 64 smem rows (stride 72) -> global h, tf32-rounded. 8 warps x 8 rows.
__device__ __forceinline__ void ln_from_smem(const float* S, int m0,
                                             const float* __restrict__ g,
                                             const float* __restrict__ b,
                                             float* __restrict__ h, int wid, int lane)
{
    float2 gg = *(const float2*)(g + lane * 2);
    float2 bb = *(const float2*)(b + lane * 2);
#pragma unroll
    for (int i = 0; i < 8; i++) {
        int r = wid * 8 + i;
        float vx = S[r * 72 + lane * 2], vy = S[r * 72 + lane * 2 + 1];
        float s  = warp_red(vx + vy);
        float mu = s * (1.0f / 64.0f);
        float dx = vx - mu, dy = vy - mu;
        float sq = warp_red(dx * dx + dy * dy);
        float inv = rsqrtf(sq * (1.0f / 64.0f) + 1e-5f);
        float2 o2 = make_float2(wmma::__float_to_tf32(dx * inv * gg.x + bb.x),
                                wmma::__float_to_tf32(dy * inv * gg.y + bb.y));
        *(float2*)(h + (size_t)(m0 + r) * C + lane * 2) = o2;
    }
}

// LN of 64 smem rows (stride 72), IN PLACE, tf32-rounded.
__device__ __forceinline__ void ln_inplace(float* S,
                                           const float* __restrict__ g,
                                           const float* __restrict__ b,
                                           int wid, int lane)
{
    float2 gg = *(const float2*)(g + lane * 2);
    float2 bb = *(const float2*)(b + lane * 2);
#pragma unroll
    for (int i = 0; i < 8; i++) {
        int r = wid * 8 + i;
        float vx = S[r * 72 + lane * 2], vy = S[r * 72 + lane * 2 + 1];
        float s  = warp_red(vx + vy);
        float mu = s * (1.0f / 64.0f);
        float dx = vx - mu, dy = vy - mu;
        float sq = warp_red(dx * dx + dy * dy);
        float inv = rsqrtf(sq * (1.0f / 64.0f) + 1e-5f);
        S[r * 72 + lane * 2]     = wmma::__float_to_tf32(dx * inv * gg.x + bb.x);
        S[r * 72 + lane * 2 + 1] = wmma::__float_to_tf32(dy * inv * gg.y + bb.y);
    }
}

// ---------------- embedding + LN1(layer0) ----------------
__global__ __launch_bounds__(256)
void embed_ln_kernel(const int* __restrict__ idx,
                     const float* __restrict__ tok,
                     const float* __restrict__ pos,
                     const float* __restrict__ g, const float* __restrict__ b,
                     float* __restrict__ x, float* __restrict__ h)
{
    int m0 = blockIdx.x * 64;
    int wid = threadIdx.x >> 5, lane = threadIdx.x & 31;
    float2 gg = *(const float2*)(g + lane * 2);
    float2 bb = *(const float2*)(b + lane * 2);
#pragma unroll
    for (int i = 0; i < 8; i++) {
        int r = m0 + wid * 8 + i;
        int tk = idx[r];
        float2 tv = *(const float2*)(tok + (size_t)tk * C + lane * 2);
        float2 pv = *(const float2*)(pos + (size_t)(r & (SEQ - 1)) * C + lane * 2);
        float vx = tv.x + pv.x, vy = tv.y + pv.y;
        *(float2*)(x + (size_t)r * C + lane * 2) = make_float2(vx, vy);
        float s  = warp_red(vx + vy);
        float mu = s * (1.0f / 64.0f);
        float dx = vx - mu, dy = vy - mu;
        float sq = warp_red(dx * dx + dy * dy);
        float inv = rsqrtf(sq * (1.0f / 64.0f) + 1e-5f);
        *(float2*)(h + (size_t)r * C + lane * 2) =
            make_float2(wmma::__float_to_tf32(dx * inv * gg.x + bb.x),
                        wmma::__float_to_tf32(dy * inv * gg.y + bb.y));
    }
}

// ---------------- QKV: grid (BT/64, 3); one output matrix per block.y ---------
__global__ __launch_bounds__(256)
void qkv_kernel(const float* __restrict__ h,
                const float* __restrict__ wq, const float* __restrict__ wk,
                const float* __restrict__ wv,
                float* __restrict__ q, float* __restrict__ k, float* __restrict__ v)
{
    __shared__ __align__(16) float Xs[64 * 72];
    __shared__ __align__(16) float Ws[64 * 72];
    int m0 = blockIdx.x * 64;
    int s  = blockIdx.y;
    int tid = threadIdx.x, wid = tid >> 5;
    int wm = wid >> 1, wn = wid & 1;

    const float* W = (s == 0) ? wq : (s == 1) ? wk : wv;
    float*       O = (s == 0) ? q  : (s == 1) ? k  : v;

    load_tile_raw(h + (size_t)m0 * C, C, Xs, 72, tid);
    load_tile_tf32(W, 64, Ws, 72, tid);
    __syncthreads();

    FragC c0, c1;
    wmma::fill_fragment(c0, 0.0f);
    wmma::fill_fragment(c1, 0.0f);
    mma_64(Xs, 72, Ws, 72, wm, wn, c0, c1);
    float* op = O + (size_t)(m0 + wm * 16) * C + wn * 32;
    wmma::store_matrix_sync(op,      c0, C, wmma::mem_row_major);
    wmma::store_matrix_sync(op + 16, c1, C, wmma::mem_row_major);
}

// ---------------- attention: max-free online softmax ----------------
__global__ __launch_bounds__(256)
void attn_kernel(const float* __restrict__ q, const float* __restrict__ k,
                 const float* __restrict__ v, float* __restrict__ o)
{
    __shared__ float4 ks[SEQ][2];
    __shared__ float4 vs[SEQ][2];
    int b = blockIdx.x >> 3;
    int h = blockIdx.x & 7;
    int t = threadIdx.x;
    size_t base = (size_t)(b * SEQ + t) * C + h * HS;

    ks[t][0] = *(const float4*)(k + base);
    ks[t][1] = *(const float4*)(k + base + 4);
    vs[t][0] = *(const float4*)(v + base);
    vs[t][1] = *(const float4*)(v + base + 4);
    float4 q0 = *(const float4*)(q + base);
    float4 q1 = *(const float4*)(q + base + 4);
    __syncthreads();

    float s = 0.0f;
    float o0 = 0, o1 = 0, o2 = 0, o3 = 0, o4 = 0, o5 = 0, o6 = 0, o7 = 0;
    for (int j = 0; j <= t; j++) {
        float4 k0 = ks[j][0], k1 = ks[j][1];
        float sc = q0.x * k0.x + q0.y * k0.y + q0.z * k0.z + q0.w * k0.w
                 + q1.x * k1.x + q1.y * k1.y + q1.z * k1.z + q1.w * k1.w;
        float p = __expf(sc * 0.125f);
        s += p;
        float4 v0 = vs[j][0], v1 = vs[j][1];
        o0 += p * v0.x;  o1 += p * v0.y;  o2 += p * v0.z;  o3 += p * v0.w;
        o4 += p * v1.x;  o5 += p * v1.y;  o6 += p * v1.z;  o7 += p * v1.w;
    }
    float inv = 1.0f / s;
    *(float4*)(o + base)     = make_float4(o0 * inv, o1 * inv, o2 * inv, o3 * inv);
    *(float4*)(o + base + 4) = make_float4(o4 * inv, o5 * inv, o6 * inv, o7 * inv);
}

// ------- fused proj + residual + LN2 + FFN1 + ReLU (all row-local) ------------
__global__ __launch_bounds__(256)
void proj_ffn1_kernel(const float* __restrict__ A,   // att
                      const float* __restrict__ Wp, const float* __restrict__ bp,
                      float* __restrict__ x,
                      const float* __restrict__ ln_g, const float* __restrict__ ln_b,
                      const float* __restrict__ W1, const float* __restrict__ b1,
                      float* __restrict__ ff)
{
    extern __shared__ __align__(16) float sm[];
    float* As  = sm;                  // 64*72  : att / x / LN(x)
    float* Ws  = sm + 64 * 72;        // 64*72  : Wp / proj C staging
    float* W1s = sm + 2 * 64 * 72;    // 64*264 : W1 / ffn1 C staging
    int m0 = blockIdx.x * 64;
    int tid = threadIdx.x, wid = tid >> 5, lane = tid & 31;
    int wm = wid >> 1, wn = wid & 1;

    // W1 first (64KB, longest load) so its LDGs fly during everything else
#pragma unroll
    for (int i = 0; i < 16; i++) {
        int u = tid + 256 * i;
        int r = u >> 6, c4 = u & 63;
        float4 w4 = *(const float4*)(W1 + (size_t)r * DFF + c4 * 4);
        float* d = &W1s[r * 264 + c4 * 4];
        d[0] = wmma::__float_to_tf32(w4.x);
        d[1] = wmma::__float_to_tf32(w4.y);
        d[2] = wmma::__float_to_tf32(w4.z);
        d[3] = wmma::__float_to_tf32(w4.w);
    }
    load_tile_tf32(A + (size_t)m0 * C, C, As, 72, tid);
    load_tile_tf32(Wp, 64, Ws, 72, tid);
    __syncthreads();

    // ---- proj ----
    FragC c0, c1;
    wmma::fill_fragment(c0, 0.0f);
    wmma::fill_fragment(c1, 0.0f);
    mma_64(As, 72, Ws, 72, wm, wn, c0, c1);
    __syncthreads();
    wmma::store_matrix_sync(&Ws[wm * 16 * 72 + wn * 32],      c0, 72, wmma::mem_row_major);
    wmma::store_matrix_sync(&Ws[wm * 16 * 72 + wn * 32 + 16], c1, 72, wmma::mem_row_major);
    __syncthreads();

    // ---- residual + bias -> x (gmem) and As (smem) ----
#pragma unroll
    for (int i = 0; i < 4; i++) {
        int u = tid + 256 * i;
        int r = u >> 4, c = (u & 15) << 2;
        float4 cv = *(float4*)&Ws[r * 72 + c];
        float4 bb = *(const float4*)(bp + c);
        size_t ro = (size_t)(m0 + r) * C + c;
        float4 rr = *(const float4*)(x + ro);
        float4 nx = make_float4(cv.x + bb.x + rr.x, cv.y + bb.y + rr.y,
                                cv.z + bb.z + rr.z, cv.w + bb.w + rr.w);
        *(float4*)(x + ro) = nx;
        *(float4*)&As[r * 72 + c] = nx;
    }
    __syncthreads();

    // ---- LN2 in place ----
    ln_inplace(As, ln_g, ln_b, wid, lane);
    __syncthreads();

    // ---- FFN1: 64x256 output; warp (m = wid&3, nb = (wid>>2)*8) ----
    int m  = wid & 3;
    int nb = (wid >> 2) * 8;
    FragC acc[8];
#pragma unroll
    for (int j = 0; j < 8; j++) wmma::fill_fragment(acc[j], 0.0f);
    FragA fa; FragB fb;
#pragma unroll
    for (int kk = 0; kk < 8; kk++) {
        wmma::load_matrix_sync(fa, &As[m * 16 * 72 + kk * 8], 72);
#pragma unroll
        for (int j = 0; j < 8; j++) {
            wmma::load_matrix_sync(fb, &W1s[kk * 8 * 264 + (nb + j) * 16], 264);
            wmma::mma_sync(acc[j], fa, fb, acc[j]);
        }
    }
    __syncthreads();
#pragma unroll
    for (int j = 0; j < 8; j++)
        wmma::store_matrix_sync(&W1s[m * 16 * 264 + (nb + j) * 16], acc[j], 264,
                                wmma::mem_row_major);
    __syncthreads();

    // ---- bias + ReLU -> ff (tf32-rounded) ----
#pragma unroll
    for (int i = 0; i < 16; i++) {
        int u = tid + 256 * i;
        int r = u >> 6, c4 = u & 63;
        float4 cv = *(float4*)&W1s[r * 264 + c4 * 4];
        float4 bb = *(const float4*)(b1 + c4 * 4);
        *(float4*)(ff + (size_t)(m0 + r) * DFF + c4 * 4) =
            make_float4(wmma::__float_to_tf32(fmaxf(cv.x + bb.x, 0.0f)),
                        wmma::__float_to_tf32(fmaxf(cv.y + bb.y, 0.0f)),
                        wmma::__float_to_tf32(fmaxf(cv.z + bb.z, 0.0f)),
                        wmma::__float_to_tf32(fmaxf(cv.w + bb.w, 0.0f)));
    }
}

// ------- FFN2 (k-chunked, reg-staged prefetch) + residual + LN_next -----------
__global__ __launch_bounds__(256)
void ffn2_kernel(const float* __restrict__ ff, const float* __restrict__ W2,
                 const float* __restrict__ b2, float* __restrict__ x,
                 const float* __restrict__ ln_g, const float* __restrict__ ln_b,
                 float* __restrict__ h)
{
    __shared__ __align__(16) float As[64 * 72];
    __shared__ __align__(16) float Ws[64 * 72];
    int m0 = blockIdx.x * 64;
    int tid = threadIdx.x, wid = tid >> 5, lane = tid & 31;
    int wm = wid >> 1, wn = wid & 1;

    float4 areg[4], wreg[4];
#pragma unroll
    for (int i = 0; i < 4; i++) {                      // prefetch chunk 0
        int u = tid + 256 * i;
        int r = u >> 4, c = (u & 15) << 2;
        areg[i] = *(const float4*)(ff + (size_t)(m0 + r) * DFF + c);
        wreg[i] = *(const float4*)(W2 + (size_t)r * C + c);
    }

    FragC c0, c1;
    wmma::fill_fragment(c0, 0.0f);
    wmma::fill_fragment(c1, 0.0f);

    for (int kc = 0; kc < 4; kc++) {
#pragma unroll
        for (int i = 0; i < 4; i++) {                  // stage regs -> smem
            int u = tid + 256 * i;
            int r = u >> 4, c = (u & 15) << 2;
            *(float4*)&As[r * 72 + c] = areg[i];       // ff already tf32-rounded
            float* d = &Ws[r * 72 + c];
            d[0] = wmma::__float_to_tf32(wreg[i].x);
            d[1] = wmma::__float_to_tf32(wreg[i].y);
            d[2] = wmma::__float_to_tf32(wreg[i].z);
            d[3] = wmma::__float_to_tf32(wreg[i].w);
        }
        __syncthreads();
        if (kc < 3) {                                  // prefetch next chunk
#pragma unroll
            for (int i = 0; i < 4; i++) {
                int u = tid + 256 * i;
                int r = u >> 4, c = (u & 15) << 2;
                areg[i] = *(const float4*)(ff + (size_t)(m0 + r) * DFF + (kc + 1) * 64 + c);
                wreg[i] = *(const float4*)(W2 + (size_t)((kc + 1) * 64 + r) * C + c);
            }
        }
        mma_64(As, 72, Ws, 72, wm, wn, c0, c1);
        __syncthreads();
    }

    wmma::store_matrix_sync(&As[wm * 16 * 72 + wn * 32],      c0, 72, wmma::mem_row_major);
    wmma::store_matrix_sync(&As[wm * 16 * 72 + wn * 32 + 16], c1, 72, wmma::mem_row_major);
    __syncthreads();

#pragma unroll
    for (int i = 0; i < 4; i++) {
        int u = tid + 256 * i;
        int r = u >> 4, c = (u & 15) << 2;
        float4 cv = *(float4*)&As[r * 72 + c];
        float4 bb = *(const float4*)(b2 + c);
        size_t ro = (size_t)(m0 + r) * C + c;
        float4 rr = *(const float4*)(x + ro);
        float4 nx = make_float4(cv.x + bb.x + rr.x, cv.y + bb.y + rr.y,
                                cv.z + bb.z + rr.z, cv.w + bb.w + rr.w);
        *(float4*)(x + ro) = nx;
        *(float4*)&As[r * 72 + c] = nx;
    }
    __syncthreads();
    ln_from_smem(As, m0, ln_g, ln_b, h, wid, lane);
}

// ------- LM head: pipelined W tiles, bias-initialized acc, direct store -------
__global__ __launch_bounds__(256)
void head_kernel(const float* __restrict__ h, const float* __restrict__ W,
                 const float* __restrict__ bias, float* __restrict__ out)
{
    extern __shared__ __align__(16) float sm[];
    float* Xs = sm;                    // 64*72
    float* Wb = sm + 64 * 72;          // 2 x 64*72
    float* Bs = sm + 3 * 64 * 72;      // 16*72 bias tile (rows replicated)
    int m0 = blockIdx.x * 64;
    int base_n = blockIdx.y * 25 * 64;
    int tid = threadIdx.x, wid = tid >> 5;
    int wm = wid >> 1, wn = wid & 1;

    load_tile_raw(h + (size_t)m0 * C, C, Xs, 72, tid);

    float4 wreg[4];
#pragma unroll
    for (int i = 0; i < 4; i++) {                      // prefetch W tile 0
        int u = tid + 256 * i;
        int r = u >> 4, c = (u & 15) << 2;
        wreg[i] = *(const float4*)(W + (size_t)r * VOCAB + base_n + c);
    }
    __syncthreads();

    {   // stage tile 0 + bias 0
#pragma unroll
        for (int i = 0; i < 4; i++) {
            int u = tid + 256 * i;
            int r = u >> 4, c = (u & 15) << 2;
            float* d = &Wb[r * 72 + c];
            d[0] = wmma::__float_to_tf32(wreg[i].x);
            d[1] = wmma::__float_to_tf32(wreg[i].y);
            d[2] = wmma::__float_to_tf32(wreg[i].z);
            d[3] = wmma::__float_to_tf32(wreg[i].w);
        }
        int r = tid >> 4, c = (tid & 15) << 2;
        *(float4*)&Bs[r * 72 + c] = *(const float4*)(bias + base_n + c);
    }
    __syncthreads();

    for (int i = 0; i < 25; i++) {
        int n0 = base_n + i * 64;
        const float* cur = Wb + (i & 1) * 64 * 72;

        if (i < 24) {                                  // prefetch next W tile
#pragma unroll
            for (int j = 0; j < 4; j++) {
                int u = tid + 256 * j;
                int r = u >> 4, c = (u & 15) << 2;
                wreg[j] = *(const float4*)(W + (size_t)r * VOCAB + n0 + 64 + c);
            }
        }

        FragC a0, a1;
        wmma::load_matrix_sync(a0, &Bs[wn * 32],      72, wmma::mem_row_major);
        wmma::load_matrix_sync(a1, &Bs[wn * 32 + 16], 72, wmma::mem_row_major);
        FragA fa; FragB fb;
#pragma unroll
        for (int kk = 0; kk < 8; kk++) {
            wmma::load_matrix_sync(fa, &Xs[wm * 16 * 72 + kk * 8], 72);
            wmma::load_matrix_sync(fb, &cur[kk * 8 * 72 + wn * 32], 72);
            wmma::mma_sync(a0, fa, fb, a0);
            wmma::load_matrix_sync(fb, &cur[kk * 8 * 72 + wn * 32 + 16], 72);
            wmma::mma_sync(a1, fa, fb, a1);
        }
        float* op = out + (size_t)(m0 + wm * 16) * VOCAB + n0 + wn * 32;
        wmma::store_matrix_sync(op,      a0, VOCAB, wmma::mem_row_major);
        wmma::store_matrix_sync(op + 16, a1, VOCAB, wmma::mem_row_major);
        __syncthreads();                               // Bs & other buf free

        if (i < 24) {                                  // stage next tile + bias
            float* nxt = Wb + ((i + 1) & 1) * 64 * 72;
#pragma unroll
            for (int j = 0; j < 4; j++) {
                int u = tid + 256 * j;
                int r = u >> 4, c = (u & 15) << 2;
                float* d = &nxt[r * 72 + c];
                d[0] = wmma::__float_to_tf32(wreg[j].x);
                d[1] = wmma::__float_to_tf32(wreg[j].y);
                d[2] = wmma::__float_to_tf32(wreg[j].z);
                d[3] = wmma::__float_to_tf32(wreg[j].w);
            }
            int r = tid >> 4, c = (tid & 15) << 2;
            *(float4*)&Bs[r * 72 + c] = *(const float4*)(bias + n0 + 64 + c);
            __syncthreads();
        }
    }
}

// ---------------- launch ----------------
extern "C" void kernel_launch(void* const* d_in, const int* in_sizes, int n_in,
                              void* d_out, int out_size)
{
    const int*   idx    = (const int*)  d_in[0];
    const float* tok    = (const float*)d_in[1];
    const float* pos    = (const float*)d_in[2];
    const float* wq     = (const float*)d_in[3];
    const float* wk     = (const float*)d_in[4];
    const float* wv     = (const float*)d_in[5];
    const float* w_proj = (const float*)d_in[6];
    const float* b_proj = (const float*)d_in[7];
    const float* ln1_g  = (const float*)d_in[8];
    const float* ln1_b  = (const float*)d_in[9];
    const float* ln2_g  = (const float*)d_in[10];
    const float* ln2_b  = (const float*)d_in[11];
    const float* w1     = (const float*)d_in[12];
    const float* b1     = (const float*)d_in[13];
    const float* w2     = (const float*)d_in[14];
    const float* b2     = (const float*)d_in[15];
    const float* lnf_g  = (const float*)d_in[16];
    const float* lnf_b  = (const float*)d_in[17];
    const float* w_head = (const float*)d_in[18];
    const float* b_head = (const float*)d_in[19];
    float* out = (float*)d_out;

    float *x, *h, *q, *k, *v, *att, *ff;
    cudaGetSymbolAddress((void**)&x,   g_x);
    cudaGetSymbolAddress((void**)&h,   g_h);
    cudaGetSymbolAddress((void**)&q,   g_q);
    cudaGetSymbolAddress((void**)&k,   g_k);
    cudaGetSymbolAddress((void**)&v,   g_v);
    cudaGetSymbolAddress((void**)&att, g_att);
    cudaGetSymbolAddress((void**)&ff,  g_ff);

    const int PF1_SMEM  = (2 * 64 * 72 + 64 * 264) * 4;      // 104,448
    const int HEAD_SMEM = (3 * 64 * 72 + 16 * 72) * 4;       //  59,904
    cudaFuncSetAttribute(proj_ffn1_kernel, cudaFuncAttributeMaxDynamicSharedMemorySize, PF1_SMEM);
    cudaFuncSetAttribute(head_kernel,      cudaFuncAttributeMaxDynamicSharedMemorySize, HEAD_SMEM);

    embed_ln_kernel<<<BT / 64, 256>>>(idx, tok, pos, ln1_g, ln1_b, x, h);

    for (int l = 0; l < NLAYER; l++) {
        qkv_kernel<<<dim3(BT / 64, 3), 256>>>(h, wq + l * 4096, wk + l * 4096,
                                              wv + l * 4096, q, k, v);
        attn_kernel<<<NBATCH * NH, 256>>>(q, k, v, att);
        proj_ffn1_kernel<<<BT / 64, 256, PF1_SMEM>>>(att, w_proj + l * 4096,
                                                     b_proj + l * 64, x,
                                                     ln2_g + l * 64, ln2_b + l * 64,
                                                     w1 + l * 64 * 256, b1 + l * 256, ff);
        const float* gn = (l < NLAYER - 1) ? (ln1_g + (l + 1) * 64) : lnf_g;
        const float* bn = (l < NLAYER - 1) ? (ln1_b + (l + 1) * 64) : lnf_b;
        ffn2_kernel<<<BT / 64, 256>>>(ff, w2 + l * 256 * 64, b2 + l * 64,
                                      x, gn, bn, h);
    }
    head_kernel<<<dim3(BT / 64, 5), 256, HEAD_SMEM>>>(h, w_head, b_head, out);
}

// round 14
// speedup vs baseline: 1.7640x; 1.0530x over previous
#include <cuda_runtime.h>
#include <cuda_bf16.h>
#include <mma.h>

using namespace nvcuda;

// ---------------- problem constants ----------------
#define NBATCH   64
#define SEQ      256
#define BT       16384
#define C        64
#define NH       8
#define HS       8
#define DFF      256
#define NLAYER   10
#define VOCAB    8000

// ---------------- scratch (static device, no allocs) ----------------
__device__ float g_x  [BT * C];     // residual stream (fp32)
__device__ float g_h  [BT * C];     // LN output feeding qkv / head (tf32-rounded)
__device__ float g_q  [BT * C];
__device__ float g_k  [BT * C];
__device__ float g_v  [BT * C];
__device__ float g_att[BT * C];
__device__ float g_ff [BT * DFF];

// ---------------- helpers ----------------
__device__ __forceinline__ float warp_red(float s) {
#pragma unroll
    for (int o = 16; o; o >>= 1) s += __shfl_xor_sync(0xffffffffu, s, o);
    return s;
}

typedef wmma::fragment<wmma::matrix_a, 16, 16, 8, wmma::precision::tf32, wmma::row_major> FragA;
typedef wmma::fragment<wmma::matrix_b, 16, 16, 8, wmma::precision::tf32, wmma::row_major> FragB;
typedef wmma::fragment<wmma::accumulator, 16, 16, 8, float> FragC;

// 64x64 fp32 tile (row stride lds) -> smem (stride ld), tf32-rounded. 256 thr.
__device__ __forceinline__ void load_tile_tf32(const float* __restrict__ src, size_t lds,
                                               float* Ds, int ld, int tid)
{
#pragma unroll
    for (int i = 0; i < 4; i++) {
        int u = tid + 256 * i;
        int r = u >> 4, c = (u & 15) << 2;
        float4 w4 = *(const float4*)(src + (size_t)r * lds + c);
        Ds[r * ld + c + 0] = wmma::__float_to_tf32(w4.x);
        Ds[r * ld + c + 1] = wmma::__float_to_tf32(w4.y);
        Ds[r * ld + c + 2] = wmma::__float_to_tf32(w4.z);
        Ds[r * ld + c + 3] = wmma::__float_to_tf32(w4.w);
    }
}

// 64x64 plain copy (values already tf32-rounded). 256 threads.
__device__ __forceinline__ void load_tile_raw(const float* __restrict__ src, size_t lds,
                                              float* Ds, int ld, int tid)
{
#pragma unroll
    for (int i = 0; i < 4; i++) {
        int u = tid + 256 * i;
        int r = u >> 4, c = (u & 15) << 2;
        *(float4*)&Ds[r * ld + c] = *(const float4*)(src + (size_t)r * lds + c);
    }
}

// 64x64x64 mma: warp (wm,wn) owns 16x32; accumulate into c0,c1.
__device__ __forceinline__ void mma_64(const float* Xs, int lda, const float* Ws, int ldb,
                                       int wm, int wn, FragC& c0, FragC& c1)
{
    FragA fa; FragB fb;
#pragma unroll
    for (int kk = 0; kk < 8; kk++) {
        wmma::load_matrix_sync(fa, &Xs[wm * 16 * lda + kk * 8], lda);
        wmma::load_matrix_sync(fb, &Ws[kk * 8 * ldb + wn * 32], ldb);
        wmma::mma_sync(c0, fa, fb, c0);
        wmma::load_matrix_sync(fb, &Ws[kk * 8 * ldb + wn * 32 + 16], ldb);
        wmma::mma_sync(c1, fa, fb, c1);
    }
}

// LN of 64 smem rows (stride 72) -> global h, tf32-rounded. 8 warps x 8 rows.
__device__ __forceinline__ void ln_from_smem(const float* S, int m0,
                                             const float* __restrict__ g,
                                             const float* __restrict__ b,
                                             float* __restrict__ h, int wid, int lane)
{
    float2 gg = *(const float2*)(g + lane * 2);
    float2 bb = *(const float2*)(b + lane * 2);
#pragma unroll
    for (int i = 0; i < 8; i++) {
        int r = wid * 8 + i;
        float vx = S[r * 72 + lane * 2], vy = S[r * 72 + lane * 2 + 1];
        float s  = warp_red(vx + vy);
        float mu = s * (1.0f / 64.0f);
        float dx = vx - mu, dy = vy - mu;
        float sq = warp_red(dx * dx + dy * dy);
        float inv = rsqrtf(sq * (1.0f / 64.0f) + 1e-5f);
        float2 o2 = make_float2(wmma::__float_to_tf32(dx * inv * gg.x + bb.x),
                                wmma::__float_to_tf32(dy * inv * gg.y + bb.y));
        *(float2*)(h + (size_t)(m0 + r) * C + lane * 2) = o2;
    }
}

// LN of 64 smem rows (stride 72), IN PLACE, tf32-rounded.
__device__ __forceinline__ void ln_inplace(float* S,
                                           const float* __restrict__ g,
                                           const float* __restrict__ b,
                                           int wid, int lane)
{
    float2 gg = *(const float2*)(g + lane * 2);
    float2 bb = *(const float2*)(b + lane * 2);
#pragma unroll
    for (int i = 0; i < 8; i++) {
        int r = wid * 8 + i;
        float vx = S[r * 72 + lane * 2], vy = S[r * 72 + lane * 2 + 1];
        float s  = warp_red(vx + vy);
        float mu = s * (1.0f / 64.0f);
        float dx = vx - mu, dy = vy - mu;
        float sq = warp_red(dx * dx + dy * dy);
        float inv = rsqrtf(sq * (1.0f / 64.0f) + 1e-5f);
        S[r * 72 + lane * 2]     = wmma::__float_to_tf32(dx * inv * gg.x + bb.x);
        S[r * 72 + lane * 2 + 1] = wmma::__float_to_tf32(dy * inv * gg.y + bb.y);
    }
}

// ---------------- embedding + LN1(layer0) ----------------
__global__ __launch_bounds__(256)
void embed_ln_kernel(const int* __restrict__ idx,
                     const float* __restrict__ tok,
                     const float* __restrict__ pos,
                     const float* __restrict__ g, const float* __restrict__ b,
                     float* __restrict__ x, float* __restrict__ h)
{
    int m0 = blockIdx.x * 64;
    int wid = threadIdx.x >> 5, lane = threadIdx.x & 31;
    float2 gg = *(const float2*)(g + lane * 2);
    float2 bb = *(const float2*)(b + lane * 2);
#pragma unroll
    for (int i = 0; i < 8; i++) {
        int r = m0 + wid * 8 + i;
        int tk = idx[r];
        float2 tv = *(const float2*)(tok + (size_t)tk * C + lane * 2);
        float2 pv = *(const float2*)(pos + (size_t)(r & (SEQ - 1)) * C + lane * 2);
        float vx = tv.x + pv.x, vy = tv.y + pv.y;
        *(float2*)(x + (size_t)r * C + lane * 2) = make_float2(vx, vy);
        float s  = warp_red(vx + vy);
        float mu = s * (1.0f / 64.0f);
        float dx = vx - mu, dy = vy - mu;
        float sq = warp_red(dx * dx + dy * dy);
        float inv = rsqrtf(sq * (1.0f / 64.0f) + 1e-5f);
        *(float2*)(h + (size_t)r * C + lane * 2) =
            make_float2(wmma::__float_to_tf32(dx * inv * gg.x + bb.x),
                        wmma::__float_to_tf32(dy * inv * gg.y + bb.y));
    }
}

// ---------------- QKV: grid (BT/64, 3); one output matrix per block.y ---------
__global__ __launch_bounds__(256)
void qkv_kernel(const float* __restrict__ h,
                const float* __restrict__ wq, const float* __restrict__ wk,
                const float* __restrict__ wv,
                float* __restrict__ q, float* __restrict__ k, float* __restrict__ v)
{
    __shared__ __align__(16) float Xs[64 * 72];
    __shared__ __align__(16) float Ws[64 * 72];
    int m0 = blockIdx.x * 64;
    int s  = blockIdx.y;
    int tid = threadIdx.x, wid = tid >> 5;
    int wm = wid >> 1, wn = wid & 1;

    const float* W = (s == 0) ? wq : (s == 1) ? wk : wv;
    float*       O = (s == 0) ? q  : (s == 1) ? k  : v;

    load_tile_raw(h + (size_t)m0 * C, C, Xs, 72, tid);
    load_tile_tf32(W, 64, Ws, 72, tid);
    __syncthreads();

    FragC c0, c1;
    wmma::fill_fragment(c0, 0.0f);
    wmma::fill_fragment(c1, 0.0f);
    mma_64(Xs, 72, Ws, 72, wm, wn, c0, c1);
    float* op = O + (size_t)(m0 + wm * 16) * C + wn * 32;
    wmma::store_matrix_sync(op,      c0, C, wmma::mem_row_major);
    wmma::store_matrix_sync(op + 16, c1, C, wmma::mem_row_major);
}

// ---------------- attention: max-free online softmax ----------------
__global__ __launch_bounds__(256)
void attn_kernel(const float* __restrict__ q, const float* __restrict__ k,
                 const float* __restrict__ v, float* __restrict__ o)
{
    __shared__ float4 ks[SEQ][2];
    __shared__ float4 vs[SEQ][2];
    int b = blockIdx.x >> 3;
    int h = blockIdx.x & 7;
    int t = threadIdx.x;
    size_t base = (size_t)(b * SEQ + t) * C + h * HS;

    ks[t][0] = *(const float4*)(k + base);
    ks[t][1] = *(const float4*)(k + base + 4);
    vs[t][0] = *(const float4*)(v + base);
    vs[t][1] = *(const float4*)(v + base + 4);
    float4 q0 = *(const float4*)(q + base);
    float4 q1 = *(const float4*)(q + base + 4);
    __syncthreads();

    float s = 0.0f;
    float o0 = 0, o1 = 0, o2 = 0, o3 = 0, o4 = 0, o5 = 0, o6 = 0, o7 = 0;
    for (int j = 0; j <= t; j++) {
        float4 k0 = ks[j][0], k1 = ks[j][1];
        float sc = q0.x * k0.x + q0.y * k0.y + q0.z * k0.z + q0.w * k0.w
                 + q1.x * k1.x + q1.y * k1.y + q1.z * k1.z + q1.w * k1.w;
        float p = __expf(sc * 0.125f);
        s += p;
        float4 v0 = vs[j][0], v1 = vs[j][1];
        o0 += p * v0.x;  o1 += p * v0.y;  o2 += p * v0.z;  o3 += p * v0.w;
        o4 += p * v1.x;  o5 += p * v1.y;  o6 += p * v1.z;  o7 += p * v1.w;
    }
    float inv = 1.0f / s;
    *(float4*)(o + base)     = make_float4(o0 * inv, o1 * inv, o2 * inv, o3 * inv);
    *(float4*)(o + base + 4) = make_float4(o4 * inv, o5 * inv, o6 * inv, o7 * inv);
}

// ------- fused proj + residual + LN2 + FFN1 + ReLU (all row-local) ------------
__global__ __launch_bounds__(256, 2)
void proj_ffn1_kernel(const float* __restrict__ A,   // att
                      const float* __restrict__ Wp, const float* __restrict__ bp,
                      float* __restrict__ x,
                      const float* __restrict__ ln_g, const float* __restrict__ ln_b,
                      const float* __restrict__ W1, const float* __restrict__ b1,
                      float* __restrict__ ff)
{
    extern __shared__ __align__(16) float sm[];
    float* As  = sm;                  // 64*72  : att / x / LN(x)
    float* Ws  = sm + 64 * 72;        // 64*72  : Wp / proj C staging
    float* W1s = sm + 2 * 64 * 72;    // 64*264 : W1 / ffn1 C staging
    int m0 = blockIdx.x * 64;
    int tid = threadIdx.x, wid = tid >> 5, lane = tid & 31;
    int wm = wid >> 1, wn = wid & 1;

    // W1 first (64KB, longest load) so its LDGs fly during everything else
#pragma unroll
    for (int i = 0; i < 16; i++) {
        int u = tid + 256 * i;
        int r = u >> 6, c4 = u & 63;
        float4 w4 = *(const float4*)(W1 + (size_t)r * DFF + c4 * 4);
        float* d = &W1s[r * 264 + c4 * 4];
        d[0] = wmma::__float_to_tf32(w4.x);
        d[1] = wmma::__float_to_tf32(w4.y);
        d[2] = wmma::__float_to_tf32(w4.z);
        d[3] = wmma::__float_to_tf32(w4.w);
    }
    load_tile_tf32(A + (size_t)m0 * C, C, As, 72, tid);
    load_tile_tf32(Wp, 64, Ws, 72, tid);
    __syncthreads();

    // ---- proj ----
    FragC c0, c1;
    wmma::fill_fragment(c0, 0.0f);
    wmma::fill_fragment(c1, 0.0f);
    mma_64(As, 72, Ws, 72, wm, wn, c0, c1);
    __syncthreads();
    wmma::store_matrix_sync(&Ws[wm * 16 * 72 + wn * 32],      c0, 72, wmma::mem_row_major);
    wmma::store_matrix_sync(&Ws[wm * 16 * 72 + wn * 32 + 16], c1, 72, wmma::mem_row_major);
    __syncthreads();

    // ---- residual + bias -> x (gmem) and As (smem) ----
#pragma unroll
    for (int i = 0; i < 4; i++) {
        int u = tid + 256 * i;
        int r = u >> 4, c = (u & 15) << 2;
        float4 cv = *(float4*)&Ws[r * 72 + c];
        float4 bb = *(const float4*)(bp + c);
        size_t ro = (size_t)(m0 + r) * C + c;
        float4 rr = *(const float4*)(x + ro);
        float4 nx = make_float4(cv.x + bb.x + rr.x, cv.y + bb.y + rr.y,
                                cv.z + bb.z + rr.z, cv.w + bb.w + rr.w);
        *(float4*)(x + ro) = nx;
        *(float4*)&As[r * 72 + c] = nx;
    }
    __syncthreads();

    // ---- LN2 in place ----
    ln_inplace(As, ln_g, ln_b, wid, lane);
    __syncthreads();

    // ---- FFN1: 64x256 output; warp (m = wid&3, nb = (wid>>2)*8) ----
    int m  = wid & 3;
    int nb = (wid >> 2) * 8;
    FragC acc[8];
#pragma unroll
    for (int j = 0; j < 8; j++) wmma::fill_fragment(acc[j], 0.0f);
    FragA fa; FragB fb;
#pragma unroll
    for (int kk = 0; kk < 8; kk++) {
        wmma::load_matrix_sync(fa, &As[m * 16 * 72 + kk * 8], 72);
#pragma unroll
        for (int j = 0; j < 8; j++) {
            wmma::load_matrix_sync(fb, &W1s[kk * 8 * 264 + (nb + j) * 16], 264);
            wmma::mma_sync(acc[j], fa, fb, acc[j]);
        }
    }
    __syncthreads();
#pragma unroll
    for (int j = 0; j < 8; j++)
        wmma::store_matrix_sync(&W1s[m * 16 * 264 + (nb + j) * 16], acc[j], 264,
                                wmma::mem_row_major);
    __syncthreads();

    // ---- bias + ReLU -> ff (tf32-rounded) ----
#pragma unroll
    for (int i = 0; i < 16; i++) {
        int u = tid + 256 * i;
        int r = u >> 6, c4 = u & 63;
        float4 cv = *(float4*)&W1s[r * 264 + c4 * 4];
        float4 bb = *(const float4*)(b1 + c4 * 4);
        *(float4*)(ff + (size_t)(m0 + r) * DFF + c4 * 4) =
            make_float4(wmma::__float_to_tf32(fmaxf(cv.x + bb.x, 0.0f)),
                        wmma::__float_to_tf32(fmaxf(cv.y + bb.y, 0.0f)),
                        wmma::__float_to_tf32(fmaxf(cv.z + bb.z, 0.0f)),
                        wmma::__float_to_tf32(fmaxf(cv.w + bb.w, 0.0f)));
    }
}

// ------- FFN2 (k-chunked, reg-staged prefetch) + residual + LN_next -----------
__global__ __launch_bounds__(256)
void ffn2_kernel(const float* __restrict__ ff, const float* __restrict__ W2,
                 const float* __restrict__ b2, float* __restrict__ x,
                 const float* __restrict__ ln_g, const float* __restrict__ ln_b,
                 float* __restrict__ h)
{
    __shared__ __align__(16) float As[64 * 72];
    __shared__ __align__(16) float Ws[64 * 72];
    int m0 = blockIdx.x * 64;
    int tid = threadIdx.x, wid = tid >> 5, lane = tid & 31;
    int wm = wid >> 1, wn = wid & 1;

    float4 areg[4], wreg[4];
#pragma unroll
    for (int i = 0; i < 4; i++) {                      // prefetch chunk 0
        int u = tid + 256 * i;
        int r = u >> 4, c = (u & 15) << 2;
        areg[i] = *(const float4*)(ff + (size_t)(m0 + r) * DFF + c);
        wreg[i] = *(const float4*)(W2 + (size_t)r * C + c);
    }

    FragC c0, c1;
    wmma::fill_fragment(c0, 0.0f);
    wmma::fill_fragment(c1, 0.0f);

    for (int kc = 0; kc < 4; kc++) {
#pragma unroll
        for (int i = 0; i < 4; i++) {                  // stage regs -> smem
            int u = tid + 256 * i;
            int r = u >> 4, c = (u & 15) << 2;
            *(float4*)&As[r * 72 + c] = areg[i];       // ff already tf32-rounded
            float* d = &Ws[r * 72 + c];
            d[0] = wmma::__float_to_tf32(wreg[i].x);
            d[1] = wmma::__float_to_tf32(wreg[i].y);
            d[2] = wmma::__float_to_tf32(wreg[i].z);
            d[3] = wmma::__float_to_tf32(wreg[i].w);
        }
        __syncthreads();
        if (kc < 3) {                                  // prefetch next chunk
#pragma unroll
            for (int i = 0; i < 4; i++) {
                int u = tid + 256 * i;
                int r = u >> 4, c = (u & 15) << 2;
                areg[i] = *(const float4*)(ff + (size_t)(m0 + r) * DFF + (kc + 1) * 64 + c);
                wreg[i] = *(const float4*)(W2 + (size_t)((kc + 1) * 64 + r) * C + c);
            }
        }
        mma_64(As, 72, Ws, 72, wm, wn, c0, c1);
        __syncthreads();
    }

    wmma::store_matrix_sync(&As[wm * 16 * 72 + wn * 32],      c0, 72, wmma::mem_row_major);
    wmma::store_matrix_sync(&As[wm * 16 * 72 + wn * 32 + 16], c1, 72, wmma::mem_row_major);
    __syncthreads();

#pragma unroll
    for (int i = 0; i < 4; i++) {
        int u = tid + 256 * i;
        int r = u >> 4, c = (u & 15) << 2;
        float4 cv = *(float4*)&As[r * 72 + c];
        float4 bb = *(const float4*)(b2 + c);
        size_t ro = (size_t)(m0 + r) * C + c;
        float4 rr = *(const float4*)(x + ro);
        float4 nx = make_float4(cv.x + bb.x + rr.x, cv.y + bb.y + rr.y,
                                cv.z + bb.z + rr.z, cv.w + bb.w + rr.w);
        *(float4*)(x + ro) = nx;
        *(float4*)&As[r * 72 + c] = nx;
    }
    __syncthreads();
    ln_from_smem(As, m0, ln_g, ln_b, h, wid, lane);
}

// ------- LM head: ONE 128x64 tile per block, grid (128,125); single sync ------
__global__ __launch_bounds__(256)
void head_kernel(const float* __restrict__ h, const float* __restrict__ W,
                 const float* __restrict__ bias, float* __restrict__ out)
{
    extern __shared__ __align__(16) float sm[];
    float* Xs = sm;                    // 128*72 = 36,864B
    float* Ws = sm + 128 * 72;         // 64*72  = 18,432B
    float* Bs = sm + 128 * 72 + 64 * 72; // 16*72 =  4,608B   (total 59,904B)
    int m0 = blockIdx.x * 128;
    int n0 = blockIdx.y * 64;
    int tid = threadIdx.x, wid = tid >> 5;

    // X panel (already tf32-rounded): 8 float4 per thread
#pragma unroll
    for (int i = 0; i < 8; i++) {
        int u = tid + 256 * i;
        int r = u >> 4, c = (u & 15) << 2;
        *(float4*)&Xs[r * 72 + c] = *(const float4*)(h + (size_t)(m0 + r) * C + c);
    }
    // W tile, tf32-rounded
#pragma unroll
    for (int i = 0; i < 4; i++) {
        int u = tid + 256 * i;
        int r = u >> 4, c = (u & 15) << 2;
        float4 w4 = *(const float4*)(W + (size_t)r * VOCAB + n0 + c);
        float* d = &Ws[r * 72 + c];
        d[0] = wmma::__float_to_tf32(w4.x);
        d[1] = wmma::__float_to_tf32(w4.y);
        d[2] = wmma::__float_to_tf32(w4.z);
        d[3] = wmma::__float_to_tf32(w4.w);
    }
    // bias tile, replicated over 16 rows (acc init via load_matrix_sync)
    {
        int r = tid >> 4, c = (tid & 15) << 2;
        *(float4*)&Bs[r * 72 + c] = *(const float4*)(bias + n0 + c);
    }
    __syncthreads();

    // warp wid owns rows [wid*16, wid*16+16), all 64 cols as 4 subtiles
    FragC acc[4];
#pragma unroll
    for (int nt = 0; nt < 4; nt++)
        wmma::load_matrix_sync(acc[nt], &Bs[nt * 16], 72, wmma::mem_row_major);

    FragA fa; FragB fb;
#pragma unroll
    for (int kk = 0; kk < 8; kk++) {
        wmma::load_matrix_sync(fa, &Xs[wid * 16 * 72 + kk * 8], 72);
#pragma unroll
        for (int nt = 0; nt < 4; nt++) {
            wmma::load_matrix_sync(fb, &Ws[kk * 8 * 72 + nt * 16], 72);
            wmma::mma_sync(acc[nt], fa, fb, acc[nt]);
        }
    }

    float* op = out + (size_t)(m0 + wid * 16) * VOCAB + n0;
#pragma unroll
    for (int nt = 0; nt < 4; nt++)
        wmma::store_matrix_sync(op + nt * 16, acc[nt], VOCAB, wmma::mem_row_major);
}

// ---------------- launch ----------------
extern "C" void kernel_launch(void* const* d_in, const int* in_sizes, int n_in,
                              void* d_out, int out_size)
{
    const int*   idx    = (const int*)  d_in[0];
    const float* tok    = (const float*)d_in[1];
    const float* pos    = (const float*)d_in[2];
    const float* wq     = (const float*)d_in[3];
    const float* wk     = (const float*)d_in[4];
    const float* wv     = (const float*)d_in[5];
    const float* w_proj = (const float*)d_in[6];
    const float* b_proj = (const float*)d_in[7];
    const float* ln1_g  = (const float*)d_in[8];
    const float* ln1_b  = (const float*)d_in[9];
    const float* ln2_g  = (const float*)d_in[10];
    const float* ln2_b  = (const float*)d_in[11];
    const float* w1     = (const float*)d_in[12];
    const float* b1     = (const float*)d_in[13];
    const float* w2     = (const float*)d_in[14];
    const float* b2     = (const float*)d_in[15];
    const float* lnf_g  = (const float*)d_in[16];
    const float* lnf_b  = (const float*)d_in[17];
    const float* w_head = (const float*)d_in[18];
    const float* b_head = (const float*)d_in[19];
    float* out = (float*)d_out;

    float *x, *h, *q, *k, *v, *att, *ff;
    cudaGetSymbolAddress((void**)&x,   g_x);
    cudaGetSymbolAddress((void**)&h,   g_h);
    cudaGetSymbolAddress((void**)&q,   g_q);
    cudaGetSymbolAddress((void**)&k,   g_k);
    cudaGetSymbolAddress((void**)&v,   g_v);
    cudaGetSymbolAddress((void**)&att, g_att);
    cudaGetSymbolAddress((void**)&ff,  g_ff);

    const int PF1_SMEM  = (2 * 64 * 72 + 64 * 264) * 4;            // 104,448
    const int HEAD_SMEM = (128 * 72 + 64 * 72 + 16 * 72) * 4;      //  59,904
    cudaFuncSetAttribute(proj_ffn1_kernel, cudaFuncAttributeMaxDynamicSharedMemorySize, PF1_SMEM);
    cudaFuncSetAttribute(head_kernel,      cudaFuncAttributeMaxDynamicSharedMemorySize, HEAD_SMEM);

    embed_ln_kernel<<<BT / 64, 256>>>(idx, tok, pos, ln1_g, ln1_b, x, h);

    for (int l = 0; l < NLAYER; l++) {
        qkv_kernel<<<dim3(BT / 64, 3), 256>>>(h, wq + l * 4096, wk + l * 4096,
                                              wv + l * 4096, q, k, v);
        attn_kernel<<<NBATCH * NH, 256>>>(q, k, v, att);
        proj_ffn1_kernel<<<BT / 64, 256, PF1_SMEM>>>(att, w_proj + l * 4096,
                                                     b_proj + l * 64, x,
                                                     ln2_g + l * 64, ln2_b + l * 64,
                                                     w1 + l * 64 * 256, b1 + l * 256, ff);
        const float* gn = (l < NLAYER - 1) ? (ln1_g + (l + 1) * 64) : lnf_g;
        const float* bn = (l < NLAYER - 1) ? (ln1_b + (l + 1) * 64) : lnf_b;
        ffn2_kernel<<<BT / 64, 256>>>(ff, w2 + l * 256 * 64, b2 + l * 64,
                                      x, gn, bn, h);
    }
    head_kernel<<<dim3(BT / 128, VOCAB / 64), 256, HEAD_SMEM>>>(h, w_head, b_head, out);
}